// round 14
// baseline (speedup 1.0000x reference)
#include <cuda_runtime.h>
#include <cuda_bf16.h>
#include <cstdint>

#define NN 50000
#define EE 800000
#define HH 128
#define PP 16
#define SCAN_B 196   // ceil(NN/256)

typedef __nv_bfloat16 bf16;

// ---------------- scratch (device globals; no allocation allowed) -----------
__device__ float g_h[NN * HH];
__device__ float g_m1[NN * HH];
__device__ float g_m2[NN * HH];
__device__ float g_macc[NN * HH];
__device__ float g_scat[NN * 2];
__device__ int   g_cnt[NN];
__device__ int   g_off[NN + 1];
__device__ int   g_cur[NN];
__device__ int   g_bsum[SCAN_B];
__device__ int   g_rows[EE];
__device__ int   g_cols[EE];
__device__ float g_bc[HH];
__device__ float g_bme[HH];
// transposed bf16 hi/lo weights: B[n][k] = W[k][n]
__device__ bf16 g_Bhi[HH * HH];      // Wc (coord)
__device__ bf16 g_Blo[HH * HH];
__device__ bf16 g_BeW1a_h[HH * HH], g_BeW1a_l[HH * HH];
__device__ bf16 g_BeW1b_h[HH * HH], g_BeW1b_l[HH * HH];
__device__ bf16 g_BnW1a_h[HH * HH], g_BnW1a_l[HH * HH];
__device__ bf16 g_BnW2_h[HH * HH],  g_BnW2_l[HH * HH];
__device__ bf16 g_BvW1_h[HH * HH],  g_BvW1_l[HH * HH];
__device__ bf16 g_BWme_h[HH * HH],  g_BWme_l[HH * HH];
// B fragment tables: [matrix][hi/lo][ (cg*8+k)*32 + lane ], cg = colgroup (n/8)
// matrices: 0 eW1a, 1 eW1b, 2 nW1a, 3 nW2, 4 vW1, 5 Wc, 6 Wme
__device__ uint2 g_F[7][2][4096];

// ---------------- PTX helpers ------------------------------------------------
__device__ __forceinline__ void red_add_v2(float* p, float a, float b) {
    asm volatile("red.global.add.v2.f32 [%0], {%1,%2};"
                 :: "l"(p), "f"(a), "f"(b) : "memory");
}
__device__ __forceinline__ uint32_t smem_u32(const void* p) {
    uint32_t a;
    asm("{ .reg .u64 t; cvta.to.shared.u64 t, %1; cvt.u32.u64 %0, t; }" : "=r"(a) : "l"(p));
    return a;
}
__device__ __forceinline__ void ldmx4(uint32_t* r, uint32_t a) {
    asm volatile("ldmatrix.sync.aligned.m8n8.x4.shared.b16 {%0,%1,%2,%3}, [%4];"
                 : "=r"(r[0]), "=r"(r[1]), "=r"(r[2]), "=r"(r[3]) : "r"(a));
}
__device__ __forceinline__ void ldmx2(uint32_t& r0, uint32_t& r1, uint32_t a) {
    asm volatile("ldmatrix.sync.aligned.m8n8.x2.shared.b16 {%0,%1}, [%2];"
                 : "=r"(r0), "=r"(r1) : "r"(a));
}
__device__ __forceinline__ void mma_bf16(float* c, const uint32_t* a, uint32_t b0, uint32_t b1) {
    asm volatile(
        "mma.sync.aligned.m16n8k16.row.col.f32.bf16.bf16.f32 "
        "{%0,%1,%2,%3}, {%4,%5,%6,%7}, {%8,%9}, {%0,%1,%2,%3};"
        : "+f"(c[0]), "+f"(c[1]), "+f"(c[2]), "+f"(c[3])
        : "r"(a[0]), "r"(a[1]), "r"(a[2]), "r"(a[3]), "r"(b0), "r"(b1));
}
__device__ __forceinline__ void hilo4(float v0, float v1, float v2, float v3,
                                      uint2& hv, uint2& lv) {
    bf16 h0 = __float2bfloat16(v0), h1 = __float2bfloat16(v1);
    bf16 h2 = __float2bfloat16(v2), h3 = __float2bfloat16(v3);
    bf16 l0 = __float2bfloat16(v0 - __bfloat162float(h0));
    bf16 l1 = __float2bfloat16(v1 - __bfloat162float(h1));
    bf16 l2 = __float2bfloat16(v2 - __bfloat162float(h2));
    bf16 l3 = __float2bfloat16(v3 - __bfloat162float(h3));
    hv.x = ((uint32_t)__bfloat16_as_ushort(h1) << 16) | __bfloat16_as_ushort(h0);
    hv.y = ((uint32_t)__bfloat16_as_ushort(h3) << 16) | __bfloat16_as_ushort(h2);
    lv.x = ((uint32_t)__bfloat16_as_ushort(l1) << 16) | __bfloat16_as_ushort(l0);
    lv.y = ((uint32_t)__bfloat16_as_ushort(l3) << 16) | __bfloat16_as_ushort(l2);
}
__device__ __forceinline__ void hilo2(float a, float b, uint32_t& h, uint32_t& l) {
    bf16 ha = __float2bfloat16(a), hb = __float2bfloat16(b);
    bf16 la = __float2bfloat16(a - __bfloat162float(ha));
    bf16 lb = __float2bfloat16(b - __bfloat162float(hb));
    h = ((uint32_t)__bfloat16_as_ushort(hb) << 16) | __bfloat16_as_ushort(ha);
    l = ((uint32_t)__bfloat16_as_ushort(lb) << 16) | __bfloat16_as_ushort(la);
}

// ---------------- sort pipeline ----------------------------------------------
__global__ void zero_cnt_scat_kernel() {
    int i = blockIdx.x * blockDim.x + threadIdx.x;
    if (i < NN) g_cnt[i] = 0;
    if (i < NN * 2) g_scat[i] = 0.f;
}

__global__ void count_kernel(const int* __restrict__ ei) {
    int e = blockIdx.x * blockDim.x + threadIdx.x;
    if (e < EE) atomicAdd(&g_cnt[ei[e]], 1);
}

__global__ void scan1_kernel() {
    __shared__ int sm[256];
    int b = blockIdx.x, t = threadIdx.x, i = b * 256 + t;
    int v = (i < NN) ? g_cnt[i] : 0;
    sm[t] = v; __syncthreads();
    for (int o = 128; o; o >>= 1) {
        if (t < o) sm[t] += sm[t + o];
        __syncthreads();
    }
    if (t == 0) g_bsum[b] = sm[0];
}

__global__ void scan2_kernel() {
    __shared__ int sm[256];
    int t = threadIdx.x;
    int v = (t < SCAN_B) ? g_bsum[t] : 0;
    sm[t] = v; __syncthreads();
    for (int o = 1; o < 256; o <<= 1) {
        int add = (t >= o) ? sm[t - o] : 0;
        __syncthreads();
        sm[t] += add;
        __syncthreads();
    }
    if (t < SCAN_B) g_bsum[t] = sm[t] - v;
    if (t == 0) g_off[NN] = EE;
}

__global__ void scan3_kernel() {
    __shared__ int sm[256];
    int b = blockIdx.x, t = threadIdx.x, i = b * 256 + t;
    int v = (i < NN) ? g_cnt[i] : 0;
    sm[t] = v; __syncthreads();
    for (int o = 1; o < 256; o <<= 1) {
        int add = (t >= o) ? sm[t - o] : 0;
        __syncthreads();
        sm[t] += add;
        __syncthreads();
    }
    if (i < NN) {
        int off = g_bsum[b] + sm[t] - v;
        g_off[i] = off;
        g_cur[i] = off;
    }
}

__global__ void scatter_kernel(const int* __restrict__ ei) {
    int e = blockIdx.x * blockDim.x + threadIdx.x;
    if (e < EE) {
        int r = ei[e];
        int pos = atomicAdd(&g_cur[r], 1);
        g_rows[pos] = r;
        g_cols[pos] = ei[EE + e];
    }
}

// ---------------- weight prep -------------------------------------------------
__global__ void prep_all_kernel(const float* __restrict__ eW1, const float* __restrict__ nW1,
                                const float* __restrict__ nW2, const float* __restrict__ vW1,
                                const float* __restrict__ eW2, const float* __restrict__ cW1,
                                const float* __restrict__ eb2, const float* __restrict__ cb1) {
    int i = blockIdx.x, j = threadIdx.x;
    int task = blockIdx.y;
    if (task < 5) {
        const float* W;
        bf16 *oh, *ol;
        switch (task) {
            case 0: W = eW1;            oh = g_BeW1a_h; ol = g_BeW1a_l; break;
            case 1: W = eW1 + 128 * HH; oh = g_BeW1b_h; ol = g_BeW1b_l; break;
            case 2: W = nW1;            oh = g_BnW1a_h; ol = g_BnW1a_l; break;
            case 3: W = nW2;            oh = g_BnW2_h;  ol = g_BnW2_l;  break;
            default: W = vW1;           oh = g_BvW1_h;  ol = g_BvW1_l;  break;
        }
        float s = W[i * HH + j];
        bf16 hi = __float2bfloat16(s);
        bf16 lo = __float2bfloat16(s - __bfloat162float(hi));
        oh[j * HH + i] = hi;
        ol[j * HH + i] = lo;
    } else if (task == 5) {
        float s = 0.f;
        for (int k = 0; k < HH; k++) s += eW2[i * HH + k] * cW1[k * HH + j];
        bf16 hi = __float2bfloat16(s);
        bf16 lo = __float2bfloat16(s - __bfloat162float(hi));
        g_Bhi[j * HH + i] = hi;
        g_Blo[j * HH + i] = lo;
        if (i == 0) {
            float t = 0.f;
            for (int k = 0; k < HH; k++) t += eb2[k] * cW1[k * HH + j];
            g_bc[j] = t + cb1[j];
        }
    } else {
        const float* nW1b = nW1 + 128 * HH;
        float s = 0.f;
        for (int k = 0; k < HH; k++) s += eW2[i * HH + k] * nW1b[k * HH + j];
        bf16 hi = __float2bfloat16(s);
        bf16 lo = __float2bfloat16(s - __bfloat162float(hi));
        g_BWme_h[j * HH + i] = hi;
        g_BWme_l[j * HH + i] = lo;
        if (i == 0) {
            float t = 0.f;
            for (int k = 0; k < HH; k++) t += eb2[k] * nW1b[k * HH + j];
            g_bme[j] = t;
        }
    }
}

#define NM_ST 272
__global__ void prep_frag_kernel() {
    extern __shared__ char smc[];
    char* S_hi = smc;
    char* S_lo = smc + 34816;
    int task = blockIdx.x, tid = threadIdx.x, wid = tid >> 5, lane = tid & 31;
    const bf16 *Bh, *Bl;
    switch (task) {
        case 0: Bh = g_BeW1a_h; Bl = g_BeW1a_l; break;
        case 1: Bh = g_BeW1b_h; Bl = g_BeW1b_l; break;
        case 2: Bh = g_BnW1a_h; Bl = g_BnW1a_l; break;
        case 3: Bh = g_BnW2_h;  Bl = g_BnW2_l;  break;
        case 4: Bh = g_BvW1_h;  Bl = g_BvW1_l;  break;
        case 5: Bh = g_Bhi;     Bl = g_Blo;     break;
        default: Bh = g_BWme_h; Bl = g_BWme_l;  break;
    }
    for (int idx = tid; idx < 8192; idx += 256) {
        int n = idx >> 6, kp = idx & 63;
        int off = n * NM_ST + kp * 4;
        *(uint32_t*)(S_hi + off) = ((const uint32_t*)Bh)[idx];
        *(uint32_t*)(S_lo + off) = ((const uint32_t*)Bl)[idx];
    }
    __syncthreads();
    uint32_t hbase = smem_u32(S_hi), lbase = smem_u32(S_lo);
    int roff = (lane & 7) * NM_ST + ((lane >> 3) & 1) * 16;
#pragma unroll
    for (int nt = 0; nt < 2; nt++)
#pragma unroll
        for (int k = 0; k < 8; k++) {
            uint32_t a = (wid * 16 + nt * 8) * NM_ST + k * 32 + roff;
            uint32_t h0, h1, l0, l1;
            ldmx2(h0, h1, hbase + a);
            ldmx2(l0, l1, lbase + a);
            int cg = wid * 2 + nt;
            g_F[task][0][(cg * 8 + k) * 32 + lane] = make_uint2(h0, h1);
            g_F[task][1][(cg * 8 + k) * 32 + lane] = make_uint2(l0, l1);
        }
}

__global__ void embed_kernel(const float* __restrict__ h0, const float* __restrict__ W,
                             const float* __restrict__ b) {
    int row = blockIdx.x * 2 + (threadIdx.x >> 7);
    int j = threadIdx.x & 127;
    if (row >= NN) return;
    float s = b[j];
#pragma unroll
    for (int k = 0; k < PP; k++) s += h0[row * PP + k] * W[k * HH + j];
    g_h[row * HH + j] = s;
}

// ---------------- 512-thread node MMA machinery -------------------------------
#define NM_A_HI 0
#define NM_A_LO 34816
#define NM_MISC 69632
#define NM_SMEM (NM_MISC + 4096)

__device__ __forceinline__ void stage_A512(char* A_hi, char* A_lo, const float* A,
                                           int m0, int tid) {
    for (int idx = tid; idx < 128 * 32; idx += 512) {
        int r = idx >> 5, c4 = (idx & 31) << 2;
        int gr = m0 + r;
        float4 v = (gr < NN) ? *(const float4*)&A[gr * HH + c4]
                             : make_float4(0.f, 0.f, 0.f, 0.f);
        uint2 hv, lv;
        hilo4(v.x, v.y, v.z, v.w, hv, lv);
        int off = r * NM_ST + c4 * 2;
        *(uint2*)(A_hi + off) = hv;
        *(uint2*)(A_lo + off) = lv;
    }
}
__device__ __forceinline__ void load_F8(uint32_t bh[8][2], uint32_t bl[8][2],
                                        const uint2* Fh, const uint2* Fl,
                                        int wid, int lane) {
#pragma unroll
    for (int k = 0; k < 8; k++) {
        uint2 v = __ldg(&Fh[(wid * 8 + k) * 32 + lane]);
        bh[k][0] = v.x; bh[k][1] = v.y;
        uint2 u = __ldg(&Fl[(wid * 8 + k) * 32 + lane]);
        bl[k][0] = u.x; bl[k][1] = u.y;
    }
}
__device__ __forceinline__ void mma_all8(float acc[8][4], uint32_t ah_base, uint32_t al_base,
                                         uint32_t bh[8][2], uint32_t bl[8][2], int lane) {
    int aroff = (lane & 15) * NM_ST + ((lane >> 4) & 1) * 16;
#pragma unroll
    for (int m = 0; m < 8; m++) {
#pragma unroll
        for (int k = 0; k < 8; k++) {
            uint32_t a = (m * 16) * NM_ST + k * 32 + aroff;
            uint32_t ahf[4], alf[4];
            ldmx4(ahf, ah_base + a);
            ldmx4(alf, al_base + a);
            mma_bf16(acc[m], ahf, bh[k][0], bh[k][1]);
            mma_bf16(acc[m], ahf, bl[k][0], bl[k][1]);
            mma_bf16(acc[m], alf, bh[k][0], bh[k][1]);
        }
    }
}
#define ZERO_ACC8(acc) \
    _Pragma("unroll") for (int m = 0; m < 8; m++) \
    _Pragma("unroll") for (int q = 0; q < 4; q++) acc[m][q] = 0.f;

// ---------------- m1/m2 dual-output GEMM -------------------------------------
__global__ void __launch_bounds__(512, 1)
node_mma_m12(const float* __restrict__ A) {
    extern __shared__ char smc[];
    char* A_hi = smc + NM_A_HI;
    char* A_lo = smc + NM_A_LO;
    const int tid = threadIdx.x;
    const int wid = tid >> 5, lane = tid & 31;
    const int m0 = blockIdx.x * 128;
    const uint32_t ah_base = smem_u32(A_hi), al_base = smem_u32(A_lo);

    stage_A512(A_hi, A_lo, A, m0, tid);
    __syncthreads();

    uint32_t bh[8][2], bl[8][2];
    float acc[8][4];
    for (int s = 0; s < 2; s++) {
        load_F8(bh, bl, g_F[s][0], g_F[s][1], wid, lane);
        ZERO_ACC8(acc);
        mma_all8(acc, ah_base, al_base, bh, bl, lane);
        float* C = s ? g_m2 : g_m1;
        int n = wid * 8 + (lane & 3) * 2;
#pragma unroll
        for (int m = 0; m < 8; m++) {
            int r0 = m0 + m * 16 + (lane >> 2);
            int r1 = r0 + 8;
            if (r0 < NN) *(float2*)&C[r0 * HH + n] = make_float2(acc[m][0], acc[m][1]);
            if (r1 < NN) *(float2*)&C[r1 * HH + n] = make_float2(acc[m][2], acc[m][3]);
        }
    }
}

// ---------------- fused t-GEMM + h-GEMM --------------------------------------
__global__ void __launch_bounds__(512, 1)
node_mma_th(const float* __restrict__ Ah, const float* __restrict__ Amacc,
            const float* __restrict__ nb1, const float* __restrict__ nb2,
            float* __restrict__ hdst) {
    extern __shared__ char smc[];
    char* A_hi = smc + NM_A_HI;
    char* A_lo = smc + NM_A_LO;
    float* bs  = (float*)(smc + NM_MISC);
    float* bs2 = bs + 128;
    const int tid = threadIdx.x;
    const int wid = tid >> 5, lane = tid & 31;
    const int m0 = blockIdx.x * 128;
    const uint32_t ah_base = smem_u32(A_hi), al_base = smem_u32(A_lo);

    if (tid < 128) { bs[tid] = nb1[tid]; bs2[tid] = g_bme[tid]; }

    uint32_t bh[8][2], bl[8][2];
    float acc[8][4];
    ZERO_ACC8(acc);

    stage_A512(A_hi, A_lo, Ah, m0, tid);
    __syncthreads();
    load_F8(bh, bl, g_F[2][0], g_F[2][1], wid, lane);
    mma_all8(acc, ah_base, al_base, bh, bl, lane);
    __syncthreads();
    stage_A512(A_hi, A_lo, Amacc, m0, tid);
    __syncthreads();
    load_F8(bh, bl, g_F[6][0], g_F[6][1], wid, lane);
    mma_all8(acc, ah_base, al_base, bh, bl, lane);
    __syncthreads();

    // write T = relu(acc + nb1 + cnt*bme) into A smem as hi/lo
    {
        int n = wid * 8 + (lane & 3) * 2;
#pragma unroll
        for (int m = 0; m < 8; m++) {
            int r0l = m * 16 + (lane >> 2);
            int r1l = r0l + 8;
            int r0 = m0 + r0l, r1 = m0 + r1l;
            float cm0 = (r0 < NN) ? (float)g_cnt[r0] : 0.f;
            float cm1 = (r1 < NN) ? (float)g_cnt[r1] : 0.f;
            float o0 = fmaxf(acc[m][0] + bs[n] + cm0 * bs2[n], 0.f);
            float o1 = fmaxf(acc[m][1] + bs[n + 1] + cm0 * bs2[n + 1], 0.f);
            float o2 = fmaxf(acc[m][2] + bs[n] + cm1 * bs2[n], 0.f);
            float o3 = fmaxf(acc[m][3] + bs[n + 1] + cm1 * bs2[n + 1], 0.f);
            uint32_t hv, lv;
            hilo2(o0, o1, hv, lv);
            *(uint32_t*)(A_hi + r0l * NM_ST + n * 2) = hv;
            *(uint32_t*)(A_lo + r0l * NM_ST + n * 2) = lv;
            hilo2(o2, o3, hv, lv);
            *(uint32_t*)(A_hi + r1l * NM_ST + n * 2) = hv;
            *(uint32_t*)(A_lo + r1l * NM_ST + n * 2) = lv;
        }
    }
    __syncthreads();

    load_F8(bh, bl, g_F[3][0], g_F[3][1], wid, lane);
    ZERO_ACC8(acc);
    mma_all8(acc, ah_base, al_base, bh, bl, lane);

    {
        int n = wid * 8 + (lane & 3) * 2;
        float b0 = __ldg(&nb2[n]), b1 = __ldg(&nb2[n + 1]);
#pragma unroll
        for (int m = 0; m < 8; m++) {
            int r0 = m0 + m * 16 + (lane >> 2);
            int r1 = r0 + 8;
            if (r0 < NN) {
                float2 rv = *(const float2*)&Ah[r0 * HH + n];
                *(float2*)&hdst[r0 * HH + n] =
                    make_float2(acc[m][0] + b0 + rv.x, acc[m][1] + b1 + rv.y);
            }
            if (r1 < NN) {
                float2 rv = *(const float2*)&Ah[r1 * HH + n];
                *(float2*)&hdst[r1 * HH + n] =
                    make_float2(acc[m][2] + b0 + rv.x, acc[m][3] + b1 + rv.y);
            }
        }
    }
}

// ---------------- fused vW1-GEMM + v epilogue --------------------------------
__global__ void __launch_bounds__(512, 1)
node_mma_v(const float* __restrict__ A, const float* __restrict__ vb1,
           const float* __restrict__ vW2, const float* __restrict__ vb2,
           float* __restrict__ outv) {
    extern __shared__ char smc[];
    char* A_hi = smc + NM_A_HI;
    char* A_lo = smc + NM_A_LO;
    float* bs = (float*)(smc + NM_MISC);
    float* w2 = bs + 128;
    float* vp = w2 + 256;
    const int tid = threadIdx.x;
    const int wid = tid >> 5, lane = tid & 31;
    const int m0 = blockIdx.x * 128;
    const uint32_t ah_base = smem_u32(A_hi), al_base = smem_u32(A_lo);

    if (tid < 128) bs[tid] = vb1[tid];
    if (tid < 256) { w2[tid] = vW2[tid]; vp[tid] = 0.f; }

    stage_A512(A_hi, A_lo, A, m0, tid);
    __syncthreads();

    uint32_t bh[8][2], bl[8][2];
    load_F8(bh, bl, g_F[4][0], g_F[4][1], wid, lane);
    float acc[8][4];
    ZERO_ACC8(acc);
    mma_all8(acc, ah_base, al_base, bh, bl, lane);

    {
        int n = wid * 8 + (lane & 3) * 2;
#pragma unroll
        for (int m = 0; m < 8; m++) {
            int r0l = m * 16 + (lane >> 2);
            int r1l = r0l + 8;
            float o0 = fmaxf(acc[m][0] + bs[n], 0.f);
            float o1 = fmaxf(acc[m][1] + bs[n + 1], 0.f);
            float o2 = fmaxf(acc[m][2] + bs[n], 0.f);
            float o3 = fmaxf(acc[m][3] + bs[n + 1], 0.f);
            float c00 = o0 * w2[n * 2 + 0] + o1 * w2[(n + 1) * 2 + 0];
            float c01 = o0 * w2[n * 2 + 1] + o1 * w2[(n + 1) * 2 + 1];
            float c10 = o2 * w2[n * 2 + 0] + o3 * w2[(n + 1) * 2 + 0];
            float c11 = o2 * w2[n * 2 + 1] + o3 * w2[(n + 1) * 2 + 1];
            c00 += __shfl_xor_sync(0xffffffffu, c00, 1);
            c00 += __shfl_xor_sync(0xffffffffu, c00, 2);
            c01 += __shfl_xor_sync(0xffffffffu, c01, 1);
            c01 += __shfl_xor_sync(0xffffffffu, c01, 2);
            c10 += __shfl_xor_sync(0xffffffffu, c10, 1);
            c10 += __shfl_xor_sync(0xffffffffu, c10, 2);
            c11 += __shfl_xor_sync(0xffffffffu, c11, 1);
            c11 += __shfl_xor_sync(0xffffffffu, c11, 2);
            if ((lane & 3) == 0) {
                atomicAdd(&vp[2 * r0l + 0], c00);
                atomicAdd(&vp[2 * r0l + 1], c01);
                atomicAdd(&vp[2 * r1l + 0], c10);
                atomicAdd(&vp[2 * r1l + 1], c11);
            }
        }
    }
    __syncthreads();
    if (tid < 128) {
        int row = m0 + tid;
        if (row < NN) {
            float d = fmaxf((float)g_cnt[row], 1.f);
            float v0 = vp[2 * tid] + vb2[0] + g_scat[2 * row] / d;
            float v1 = vp[2 * tid + 1] + vb2[1] + g_scat[2 * row + 1] / d;
            float n = fmaxf(sqrtf(v0 * v0 + v1 * v1), 1e-12f);
            outv[2 * row] = v0 / n;
            outv[2 * row + 1] = v1 / n;
        }
    }
}

// ---------------- macc gather: one warp per node, 2-way unrolled -------------
__global__ void macc_gather_kernel(const float* __restrict__ x,
                                   const float* __restrict__ eW1,
                                   const float* __restrict__ eb1) {
    int warp = (blockIdx.x * blockDim.x + threadIdx.x) >> 5;
    int lane = threadIdx.x & 31;
    if (warp >= NN) return;
    int r = warp;
    int j = lane << 2;
    float4 m1v = *(const float4*)&g_m1[r * HH + j];
    float4 wd  = *(const float4*)&eW1[256 * HH + j];
    float4 b1  = *(const float4*)&eb1[j];
    float2 xr  = *(const float2*)&x[2 * r];
    float4 acc = make_float4(0.f, 0.f, 0.f, 0.f);
    int s = g_off[r], e = g_off[r + 1];
    int idx = s;
    for (; idx + 1 < e; idx += 2) {
        int c0 = __ldg(&g_cols[idx]);
        int c1 = __ldg(&g_cols[idx + 1]);
        float2 xc0 = *(const float2*)&x[2 * c0];
        float2 xc1 = *(const float2*)&x[2 * c1];
        float4 m2a = *(const float4*)&g_m2[c0 * HH + j];
        float4 m2b = *(const float4*)&g_m2[c1 * HH + j];
        float dx0 = xr.x - xc0.x, dy0 = xr.y - xc0.y;
        float dx1 = xr.x - xc1.x, dy1 = xr.y - xc1.y;
        float rd0 = dx0 * dx0 + dy0 * dy0;
        float rd1 = dx1 * dx1 + dy1 * dy1;
        acc.x += fmaxf(m1v.x + m2a.x + rd0 * wd.x + b1.x, 0.f)
               + fmaxf(m1v.x + m2b.x + rd1 * wd.x + b1.x, 0.f);
        acc.y += fmaxf(m1v.y + m2a.y + rd0 * wd.y + b1.y, 0.f)
               + fmaxf(m1v.y + m2b.y + rd1 * wd.y + b1.y, 0.f);
        acc.z += fmaxf(m1v.z + m2a.z + rd0 * wd.z + b1.z, 0.f)
               + fmaxf(m1v.z + m2b.z + rd1 * wd.z + b1.z, 0.f);
        acc.w += fmaxf(m1v.w + m2a.w + rd0 * wd.w + b1.w, 0.f)
               + fmaxf(m1v.w + m2b.w + rd1 * wd.w + b1.w, 0.f);
    }
    if (idx < e) {
        int c = __ldg(&g_cols[idx]);
        float2 xc = *(const float2*)&x[2 * c];
        float dx = xr.x - xc.x, dy = xr.y - xc.y;
        float rd = dx * dx + dy * dy;
        float4 m2v = *(const float4*)&g_m2[c * HH + j];
        acc.x += fmaxf(m1v.x + m2v.x + rd * wd.x + b1.x, 0.f);
        acc.y += fmaxf(m1v.y + m2v.y + rd * wd.y + b1.y, 0.f);
        acc.z += fmaxf(m1v.z + m2v.z + rd * wd.z + b1.z, 0.f);
        acc.w += fmaxf(m1v.w + m2v.w + rd * wd.w + b1.w, 0.f);
    }
    *(float4*)&g_macc[r * HH + j] = acc;
}

// ---------------- coord kernel (layer 2, 512 threads, mma.sync) --------------
#define EK2_ASTRIDE 272
#define EK2_A_HI 0
#define EK2_A_LO 34816
#define EK2_MISC 69632
#define EK2_SMEM (EK2_MISC + 5120)

__global__ void __launch_bounds__(512, 1)
edge2_kernel(const float* __restrict__ x,
             const float* __restrict__ eW1, const float* __restrict__ eb1,
             const float* __restrict__ cW2, const float* __restrict__ cb2) {
    extern __shared__ char smc[];
    char* A_hi = smc + EK2_A_HI;
    char* A_lo = smc + EK2_A_LO;
    float* misc   = (float*)(smc + EK2_MISC);
    float* wd_s   = misc;
    float* b1_s   = misc + 128;
    float* bc_s   = misc + 256;
    float* cw2_s  = misc + 384;
    float* p2a_s  = misc + 512;
    float* p2b_s  = misc + 640;
    float* rd_s   = misc + 768;
    float* coordp = misc + 896;
    int* row_s = (int*)(misc + 1024);
    int* col_s = (int*)(misc + 1152);

    const int tid = threadIdx.x;
    const int wid = tid >> 5, lane = tid & 31;

    if (tid < 128) {
        wd_s[tid]  = eW1[256 * HH + tid];
        b1_s[tid]  = eb1[tid];
        bc_s[tid]  = g_bc[tid];
        cw2_s[tid] = cW2[tid];
        coordp[tid] = 0.f;
        int eg = blockIdx.x * 128 + tid;
        int r = g_rows[eg], c = g_cols[eg];
        row_s[tid] = r; col_s[tid] = c;
        float2 xr = *(const float2*)&x[2 * r];
        float2 xc = *(const float2*)&x[2 * c];
        float dx = xr.x - xc.x, dy = xr.y - xc.y;
        rd_s[tid]  = dx * dx + dy * dy;
        p2a_s[tid] = dx * dx - dy * dy;
        p2b_s[tid] = 2.f * dx * dy;
    }
    // B fragments from table (matrix 5 = Wc): warp w owns cols [w*8, w*8+8)
    uint32_t bh[8][2], bl[8][2];
    load_F8(bh, bl, g_F[5][0], g_F[5][1], wid, lane);
    __syncthreads();

    // phase 1: preact, write A tiles (512 threads: 8 iterations)
#pragma unroll
    for (int s = 0; s < 8; s++) {
        int item = tid + s * 512;
        int e = item >> 5, j = (item & 31) << 2;
        int r = row_s[e], c = col_s[e];
        float rd = rd_s[e];
        float4 a  = *(const float4*)&g_m1[r * HH + j];
        float4 b  = *(const float4*)&g_m2[c * HH + j];
        float4 w  = *(const float4*)&wd_s[j];
        float4 bb = *(const float4*)&b1_s[j];
        float v0 = fmaxf(a.x + b.x + rd * w.x + bb.x, 0.f);
        float v1 = fmaxf(a.y + b.y + rd * w.y + bb.y, 0.f);
        float v2 = fmaxf(a.z + b.z + rd * w.z + bb.z, 0.f);
        float v3 = fmaxf(a.w + b.w + rd * w.w + bb.w, 0.f);
        uint2 hv, lv;
        hilo4(v0, v1, v2, v3, hv, lv);
        int off = e * EK2_ASTRIDE + j * 2;
        *(uint2*)(A_hi + off) = hv;
        *(uint2*)(A_lo + off) = lv;
    }
    __syncthreads();

    // phase 2: C = A @ Wc via mma, fused coord dot + scatter
    {
        uint32_t hbase = smem_u32(A_hi);
        uint32_t lbase = smem_u32(A_lo);
        int aroff = (lane & 15) * EK2_ASTRIDE + ((lane >> 4) & 1) * 16;
        int n = wid * 8 + (lane & 3) * 2;
#pragma unroll
        for (int m = 0; m < 8; m++) {
            float acc[4];
#pragma unroll
            for (int q = 0; q < 4; q++) acc[q] = 0.f;
#pragma unroll
            for (int k = 0; k < 8; k++) {
                uint32_t a = (m * 16) * EK2_ASTRIDE + k * 32 + aroff;
                uint32_t ah[4], al[4];
                ldmx4(ah, hbase + a);
                ldmx4(al, lbase + a);
                mma_bf16(acc, ah, bh[k][0], bh[k][1]);
                mma_bf16(acc, ah, bl[k][0], bl[k][1]);
                mma_bf16(acc, al, bh[k][0], bh[k][1]);
            }
            int r0 = m * 16 + (lane >> 2);
            float p0 = fmaxf(acc[0] + bc_s[n], 0.f) * cw2_s[n]
                     + fmaxf(acc[1] + bc_s[n + 1], 0.f) * cw2_s[n + 1];
            float p1 = fmaxf(acc[2] + bc_s[n], 0.f) * cw2_s[n]
                     + fmaxf(acc[3] + bc_s[n + 1], 0.f) * cw2_s[n + 1];
            p0 += __shfl_xor_sync(0xffffffffu, p0, 1);
            p0 += __shfl_xor_sync(0xffffffffu, p0, 2);
            p1 += __shfl_xor_sync(0xffffffffu, p1, 1);
            p1 += __shfl_xor_sync(0xffffffffu, p1, 2);
            if ((lane & 3) == 0) {
                atomicAdd(&coordp[r0], p0);
                atomicAdd(&coordp[r0 + 8], p1);
            }
        }
    }
    __syncthreads();
    if (tid < 128) {
        float csum = coordp[tid] + cb2[0];
        red_add_v2(&g_scat[2 * row_s[tid]], p2a_s[tid] * csum, p2b_s[tid] * csum);
    }
}

__global__ void copy_x_kernel(const float* __restrict__ x, float* __restrict__ outx) {
    int i = blockIdx.x * blockDim.x + threadIdx.x;
    if (i < NN * 2) outx[i] = x[i];
}

// ---------------- launcher ---------------------------------------------------
extern "C" void kernel_launch(void* const* d_in, const int* in_sizes, int n_in,
                              void* d_out, int out_size) {
    const float* h0   = (const float*)d_in[0];
    const float* x    = (const float*)d_in[1];
    const int*   ei   = (const int*)d_in[2];
    const float* embW = (const float*)d_in[3];
    const float* embB = (const float*)d_in[4];
    const float* eW1  = (const float*)d_in[5];
    const float* eb1  = (const float*)d_in[6];
    const float* eW2  = (const float*)d_in[7];
    const float* eb2  = (const float*)d_in[8];
    const float* nW1  = (const float*)d_in[9];
    const float* nb1  = (const float*)d_in[10];
    const float* nW2  = (const float*)d_in[11];
    const float* nb2  = (const float*)d_in[12];
    const float* vW1  = (const float*)d_in[13];
    const float* vb1  = (const float*)d_in[14];
    const float* vW2  = (const float*)d_in[15];
    const float* vb2  = (const float*)d_in[16];
    const float* cW1  = (const float*)d_in[17];
    const float* cb1  = (const float*)d_in[18];
    const float* cW2  = (const float*)d_in[19];
    const float* cb2  = (const float*)d_in[20];

    float* out   = (float*)d_out;
    float* out_h = out;
    float* out_x = out + NN * HH;
    float* out_v = out + NN * HH + NN * 2;

    float *p_h, *p_macc;
    cudaGetSymbolAddress((void**)&p_h,    g_h);
    cudaGetSymbolAddress((void**)&p_macc, g_macc);

    cudaFuncSetAttribute(node_mma_m12, cudaFuncAttributeMaxDynamicSharedMemorySize, NM_SMEM);
    cudaFuncSetAttribute(node_mma_th, cudaFuncAttributeMaxDynamicSharedMemorySize, NM_SMEM);
    cudaFuncSetAttribute(node_mma_v, cudaFuncAttributeMaxDynamicSharedMemorySize, NM_SMEM);
    cudaFuncSetAttribute(edge2_kernel, cudaFuncAttributeMaxDynamicSharedMemorySize, EK2_SMEM);
    cudaFuncSetAttribute(prep_frag_kernel, cudaFuncAttributeMaxDynamicSharedMemorySize, 69632);

    const int GB = (NN + 127) / 128;

    // side streams + events, created fresh every call and destroyed before return
    cudaStream_t s1, s2;
    cudaStreamCreateWithFlags(&s1, cudaStreamNonBlocking);
    cudaStreamCreateWithFlags(&s2, cudaStreamNonBlocking);
    cudaEvent_t eFork, eSort, eFork2, eEdge, eEmb;
    cudaEventCreateWithFlags(&eFork,  cudaEventDisableTiming);
    cudaEventCreateWithFlags(&eSort,  cudaEventDisableTiming);
    cudaEventCreateWithFlags(&eFork2, cudaEventDisableTiming);
    cudaEventCreateWithFlags(&eEdge,  cudaEventDisableTiming);
    cudaEventCreateWithFlags(&eEmb,   cudaEventDisableTiming);

    cudaEventRecord(eFork, 0);

    // --- branch s1: sort pipeline ---
    cudaStreamWaitEvent(s1, eFork, 0);
    zero_cnt_scat_kernel<<<(NN * 2 + 255) / 256, 256, 0, s1>>>();
    count_kernel<<<(EE + 255) / 256, 256, 0, s1>>>(ei);
    scan1_kernel<<<SCAN_B, 256, 0, s1>>>();
    scan2_kernel<<<1, 256, 0, s1>>>();
    scan3_kernel<<<SCAN_B, 256, 0, s1>>>();
    scatter_kernel<<<(EE + 255) / 256, 256, 0, s1>>>(ei);
    cudaEventRecord(eSort, s1);

    // --- branch s2: copy x out + embed (input-only dependencies) ---
    cudaStreamWaitEvent(s2, eFork, 0);
    copy_x_kernel<<<(NN * 2 + 255) / 256, 256, 0, s2>>>(x, out_x);
    embed_kernel<<<NN / 2, 256, 0, s2>>>(h0, embW, embB);
    cudaEventRecord(eEmb, s2);

    // --- main: weight prep (transpose, then fragment tables) ---
    {
        dim3 g(128, 7);
        prep_all_kernel<<<g, 128>>>(eW1, nW1, nW2, vW1, eW2, cW1, eb2, cb1);
    }
    prep_frag_kernel<<<7, 256, 69632>>>();

    // ---- layer 0 ----
    cudaStreamWaitEvent(0, eEmb, 0);
    node_mma_m12<<<GB, 512, NM_SMEM>>>(p_h);
    cudaStreamWaitEvent(0, eSort, 0);
    macc_gather_kernel<<<(NN * 32 + 255) / 256, 256>>>(x, eW1, eb1);
    node_mma_th<<<GB, 512, NM_SMEM>>>(p_h, p_macc, nb1, nb2, p_h);

    // ---- layer 1 ----
    node_mma_m12<<<GB, 512, NM_SMEM>>>(p_h);
    cudaEventRecord(eFork2, 0);
    cudaStreamWaitEvent(s1, eFork2, 0);
    edge2_kernel<<<EE / 128, 512, EK2_SMEM, s1>>>(x, eW1, eb1, cW2, cb2);
    cudaEventRecord(eEdge, s1);
    macc_gather_kernel<<<(NN * 32 + 255) / 256, 256>>>(x, eW1, eb1);
    node_mma_th<<<GB, 512, NM_SMEM>>>(p_h, p_macc, nb1, nb2, out_h);

    // join: v epilogue needs edge2's g_scat and th's out_h
    cudaStreamWaitEvent(0, eEdge, 0);
    node_mma_v<<<GB, 512, NM_SMEM>>>(out_h, vb1, vW2, vb2, out_v);

    // cleanup (allocation guard: return device memory to baseline)
    cudaEventDestroy(eFork);
    cudaEventDestroy(eSort);
    cudaEventDestroy(eFork2);
    cudaEventDestroy(eEdge);
    cudaEventDestroy(eEmb);
    cudaStreamDestroy(s1);
    cudaStreamDestroy(s2);
}

// round 15
// speedup vs baseline: 1.0850x; 1.0850x over previous
#include <cuda_runtime.h>
#include <cuda_bf16.h>
#include <cstdint>

#define NN 50000
#define EE 800000
#define HH 128
#define PP 16
#define SCAN_B 196   // ceil(NN/256)

typedef __nv_bfloat16 bf16;

// ---------------- scratch (device globals; no allocation allowed) -----------
__device__ float g_h[NN * HH];
__device__ float g_m1[NN * HH];
__device__ float g_m2[NN * HH];
__device__ float g_macc[NN * HH];
__device__ float g_scat[NN * 2];
__device__ int   g_cnt[NN];
__device__ int   g_off[NN + 1];
__device__ int   g_cur[NN];
__device__ int   g_bsum[SCAN_B];
__device__ int   g_rows[EE];
__device__ int   g_cols[EE];
__device__ float g_bc[HH];
__device__ float g_bme[HH];
// transposed bf16 hi/lo weights: B[n][k] = W[k][n]
__device__ bf16 g_Bhi[HH * HH];      // Wc (coord)
__device__ bf16 g_Blo[HH * HH];
__device__ bf16 g_BeW1a_h[HH * HH], g_BeW1a_l[HH * HH];
__device__ bf16 g_BeW1b_h[HH * HH], g_BeW1b_l[HH * HH];
__device__ bf16 g_BnW1a_h[HH * HH], g_BnW1a_l[HH * HH];
__device__ bf16 g_BnW2_h[HH * HH],  g_BnW2_l[HH * HH];
__device__ bf16 g_BvW1_h[HH * HH],  g_BvW1_l[HH * HH];
__device__ bf16 g_BWme_h[HH * HH],  g_BWme_l[HH * HH];
// B fragment tables: [matrix][hi/lo][ (cg*8+k)*32 + lane ], cg = colgroup (n/8)
// matrices: 0 eW1a, 1 eW1b, 2 nW1a, 3 nW2, 4 vW1, 5 Wc, 6 Wme
__device__ uint2 g_F[7][2][4096];

// ---------------- PTX helpers ------------------------------------------------
__device__ __forceinline__ void red_add_v2(float* p, float a, float b) {
    asm volatile("red.global.add.v2.f32 [%0], {%1,%2};"
                 :: "l"(p), "f"(a), "f"(b) : "memory");
}
__device__ __forceinline__ uint32_t smem_u32(const void* p) {
    uint32_t a;
    asm("{ .reg .u64 t; cvta.to.shared.u64 t, %1; cvt.u32.u64 %0, t; }" : "=r"(a) : "l"(p));
    return a;
}
__device__ __forceinline__ void ldmx4(uint32_t* r, uint32_t a) {
    asm volatile("ldmatrix.sync.aligned.m8n8.x4.shared.b16 {%0,%1,%2,%3}, [%4];"
                 : "=r"(r[0]), "=r"(r[1]), "=r"(r[2]), "=r"(r[3]) : "r"(a));
}
__device__ __forceinline__ void ldmx2(uint32_t& r0, uint32_t& r1, uint32_t a) {
    asm volatile("ldmatrix.sync.aligned.m8n8.x2.shared.b16 {%0,%1}, [%2];"
                 : "=r"(r0), "=r"(r1) : "r"(a));
}
__device__ __forceinline__ void mma_bf16(float* c, const uint32_t* a, uint32_t b0, uint32_t b1) {
    asm volatile(
        "mma.sync.aligned.m16n8k16.row.col.f32.bf16.bf16.f32 "
        "{%0,%1,%2,%3}, {%4,%5,%6,%7}, {%8,%9}, {%0,%1,%2,%3};"
        : "+f"(c[0]), "+f"(c[1]), "+f"(c[2]), "+f"(c[3])
        : "r"(a[0]), "r"(a[1]), "r"(a[2]), "r"(a[3]), "r"(b0), "r"(b1));
}
__device__ __forceinline__ void hilo4(float v0, float v1, float v2, float v3,
                                      uint2& hv, uint2& lv) {
    bf16 h0 = __float2bfloat16(v0), h1 = __float2bfloat16(v1);
    bf16 h2 = __float2bfloat16(v2), h3 = __float2bfloat16(v3);
    bf16 l0 = __float2bfloat16(v0 - __bfloat162float(h0));
    bf16 l1 = __float2bfloat16(v1 - __bfloat162float(h1));
    bf16 l2 = __float2bfloat16(v2 - __bfloat162float(h2));
    bf16 l3 = __float2bfloat16(v3 - __bfloat162float(h3));
    hv.x = ((uint32_t)__bfloat16_as_ushort(h1) << 16) | __bfloat16_as_ushort(h0);
    hv.y = ((uint32_t)__bfloat16_as_ushort(h3) << 16) | __bfloat16_as_ushort(h2);
    lv.x = ((uint32_t)__bfloat16_as_ushort(l1) << 16) | __bfloat16_as_ushort(l0);
    lv.y = ((uint32_t)__bfloat16_as_ushort(l3) << 16) | __bfloat16_as_ushort(l2);
}
__device__ __forceinline__ void hilo2(float a, float b, uint32_t& h, uint32_t& l) {
    bf16 ha = __float2bfloat16(a), hb = __float2bfloat16(b);
    bf16 la = __float2bfloat16(a - __bfloat162float(ha));
    bf16 lb = __float2bfloat16(b - __bfloat162float(hb));
    h = ((uint32_t)__bfloat16_as_ushort(hb) << 16) | __bfloat16_as_ushort(ha);
    l = ((uint32_t)__bfloat16_as_ushort(lb) << 16) | __bfloat16_as_ushort(la);
}

// ---------------- sort pipeline ----------------------------------------------
__global__ void zero_cnt_scat_kernel() {
    int i = blockIdx.x * blockDim.x + threadIdx.x;
    if (i < NN) g_cnt[i] = 0;
    if (i < NN * 2) g_scat[i] = 0.f;
}

__global__ void count_kernel(const int* __restrict__ ei) {
    int e = blockIdx.x * blockDim.x + threadIdx.x;
    if (e < EE) atomicAdd(&g_cnt[ei[e]], 1);
}

__global__ void scan1_kernel() {
    __shared__ int sm[256];
    int b = blockIdx.x, t = threadIdx.x, i = b * 256 + t;
    int v = (i < NN) ? g_cnt[i] : 0;
    sm[t] = v; __syncthreads();
    for (int o = 128; o; o >>= 1) {
        if (t < o) sm[t] += sm[t + o];
        __syncthreads();
    }
    if (t == 0) g_bsum[b] = sm[0];
}

__global__ void scan2_kernel() {
    __shared__ int sm[256];
    int t = threadIdx.x;
    int v = (t < SCAN_B) ? g_bsum[t] : 0;
    sm[t] = v; __syncthreads();
    for (int o = 1; o < 256; o <<= 1) {
        int add = (t >= o) ? sm[t - o] : 0;
        __syncthreads();
        sm[t] += add;
        __syncthreads();
    }
    if (t < SCAN_B) g_bsum[t] = sm[t] - v;
    if (t == 0) g_off[NN] = EE;
}

__global__ void scan3_kernel() {
    __shared__ int sm[256];
    int b = blockIdx.x, t = threadIdx.x, i = b * 256 + t;
    int v = (i < NN) ? g_cnt[i] : 0;
    sm[t] = v; __syncthreads();
    for (int o = 1; o < 256; o <<= 1) {
        int add = (t >= o) ? sm[t - o] : 0;
        __syncthreads();
        sm[t] += add;
        __syncthreads();
    }
    if (i < NN) {
        int off = g_bsum[b] + sm[t] - v;
        g_off[i] = off;
        g_cur[i] = off;
    }
}

__global__ void scatter_kernel(const int* __restrict__ ei) {
    int e = blockIdx.x * blockDim.x + threadIdx.x;
    if (e < EE) {
        int r = ei[e];
        int pos = atomicAdd(&g_cur[r], 1);
        g_rows[pos] = r;
        g_cols[pos] = ei[EE + e];
    }
}

// ---------------- weight prep -------------------------------------------------
__global__ void prep_all_kernel(const float* __restrict__ eW1, const float* __restrict__ nW1,
                                const float* __restrict__ nW2, const float* __restrict__ vW1,
                                const float* __restrict__ eW2, const float* __restrict__ cW1,
                                const float* __restrict__ eb2, const float* __restrict__ cb1) {
    int i = blockIdx.x, j = threadIdx.x;
    int task = blockIdx.y;
    if (task < 5) {
        const float* W;
        bf16 *oh, *ol;
        switch (task) {
            case 0: W = eW1;            oh = g_BeW1a_h; ol = g_BeW1a_l; break;
            case 1: W = eW1 + 128 * HH; oh = g_BeW1b_h; ol = g_BeW1b_l; break;
            case 2: W = nW1;            oh = g_BnW1a_h; ol = g_BnW1a_l; break;
            case 3: W = nW2;            oh = g_BnW2_h;  ol = g_BnW2_l;  break;
            default: W = vW1;           oh = g_BvW1_h;  ol = g_BvW1_l;  break;
        }
        float s = W[i * HH + j];
        bf16 hi = __float2bfloat16(s);
        bf16 lo = __float2bfloat16(s - __bfloat162float(hi));
        oh[j * HH + i] = hi;
        ol[j * HH + i] = lo;
    } else if (task == 5) {
        float s = 0.f;
        for (int k = 0; k < HH; k++) s += eW2[i * HH + k] * cW1[k * HH + j];
        bf16 hi = __float2bfloat16(s);
        bf16 lo = __float2bfloat16(s - __bfloat162float(hi));
        g_Bhi[j * HH + i] = hi;
        g_Blo[j * HH + i] = lo;
        if (i == 0) {
            float t = 0.f;
            for (int k = 0; k < HH; k++) t += eb2[k] * cW1[k * HH + j];
            g_bc[j] = t + cb1[j];
        }
    } else {
        const float* nW1b = nW1 + 128 * HH;
        float s = 0.f;
        for (int k = 0; k < HH; k++) s += eW2[i * HH + k] * nW1b[k * HH + j];
        bf16 hi = __float2bfloat16(s);
        bf16 lo = __float2bfloat16(s - __bfloat162float(hi));
        g_BWme_h[j * HH + i] = hi;
        g_BWme_l[j * HH + i] = lo;
        if (i == 0) {
            float t = 0.f;
            for (int k = 0; k < HH; k++) t += eb2[k] * nW1b[k * HH + j];
            g_bme[j] = t;
        }
    }
}

#define NM_ST 272
__global__ void prep_frag_kernel() {
    extern __shared__ char smc[];
    char* S_hi = smc;
    char* S_lo = smc + 34816;
    int task = blockIdx.x, tid = threadIdx.x, wid = tid >> 5, lane = tid & 31;
    const bf16 *Bh, *Bl;
    switch (task) {
        case 0: Bh = g_BeW1a_h; Bl = g_BeW1a_l; break;
        case 1: Bh = g_BeW1b_h; Bl = g_BeW1b_l; break;
        case 2: Bh = g_BnW1a_h; Bl = g_BnW1a_l; break;
        case 3: Bh = g_BnW2_h;  Bl = g_BnW2_l;  break;
        case 4: Bh = g_BvW1_h;  Bl = g_BvW1_l;  break;
        case 5: Bh = g_Bhi;     Bl = g_Blo;     break;
        default: Bh = g_BWme_h; Bl = g_BWme_l;  break;
    }
    for (int idx = tid; idx < 8192; idx += 256) {
        int n = idx >> 6, kp = idx & 63;
        int off = n * NM_ST + kp * 4;
        *(uint32_t*)(S_hi + off) = ((const uint32_t*)Bh)[idx];
        *(uint32_t*)(S_lo + off) = ((const uint32_t*)Bl)[idx];
    }
    __syncthreads();
    uint32_t hbase = smem_u32(S_hi), lbase = smem_u32(S_lo);
    int roff = (lane & 7) * NM_ST + ((lane >> 3) & 1) * 16;
#pragma unroll
    for (int nt = 0; nt < 2; nt++)
#pragma unroll
        for (int k = 0; k < 8; k++) {
            uint32_t a = (wid * 16 + nt * 8) * NM_ST + k * 32 + roff;
            uint32_t h0, h1, l0, l1;
            ldmx2(h0, h1, hbase + a);
            ldmx2(l0, l1, lbase + a);
            int cg = wid * 2 + nt;
            g_F[task][0][(cg * 8 + k) * 32 + lane] = make_uint2(h0, h1);
            g_F[task][1][(cg * 8 + k) * 32 + lane] = make_uint2(l0, l1);
        }
}

__global__ void embed_kernel(const float* __restrict__ h0, const float* __restrict__ W,
                             const float* __restrict__ b) {
    int row = blockIdx.x * 2 + (threadIdx.x >> 7);
    int j = threadIdx.x & 127;
    if (row >= NN) return;
    float s = b[j];
#pragma unroll
    for (int k = 0; k < PP; k++) s += h0[row * PP + k] * W[k * HH + j];
    g_h[row * HH + j] = s;
}

// ---------------- 512-thread node MMA machinery -------------------------------
#define NM_A_HI 0
#define NM_A_LO 34816
#define NM_MISC 69632
#define NM_SMEM (NM_MISC + 4096)

__device__ __forceinline__ void stage_A512(char* A_hi, char* A_lo, const float* A,
                                           int m0, int tid) {
    for (int idx = tid; idx < 128 * 32; idx += 512) {
        int r = idx >> 5, c4 = (idx & 31) << 2;
        int gr = m0 + r;
        float4 v = (gr < NN) ? *(const float4*)&A[gr * HH + c4]
                             : make_float4(0.f, 0.f, 0.f, 0.f);
        uint2 hv, lv;
        hilo4(v.x, v.y, v.z, v.w, hv, lv);
        int off = r * NM_ST + c4 * 2;
        *(uint2*)(A_hi + off) = hv;
        *(uint2*)(A_lo + off) = lv;
    }
}
__device__ __forceinline__ void load_F8(uint32_t bh[8][2], uint32_t bl[8][2],
                                        const uint2* Fh, const uint2* Fl,
                                        int wid, int lane) {
#pragma unroll
    for (int k = 0; k < 8; k++) {
        uint2 v = __ldg(&Fh[(wid * 8 + k) * 32 + lane]);
        bh[k][0] = v.x; bh[k][1] = v.y;
        uint2 u = __ldg(&Fl[(wid * 8 + k) * 32 + lane]);
        bl[k][0] = u.x; bl[k][1] = u.y;
    }
}
__device__ __forceinline__ void mma_all8(float acc[8][4], uint32_t ah_base, uint32_t al_base,
                                         uint32_t bh[8][2], uint32_t bl[8][2], int lane) {
    int aroff = (lane & 15) * NM_ST + ((lane >> 4) & 1) * 16;
#pragma unroll
    for (int m = 0; m < 8; m++) {
#pragma unroll
        for (int k = 0; k < 8; k++) {
            uint32_t a = (m * 16) * NM_ST + k * 32 + aroff;
            uint32_t ahf[4], alf[4];
            ldmx4(ahf, ah_base + a);
            ldmx4(alf, al_base + a);
            mma_bf16(acc[m], ahf, bh[k][0], bh[k][1]);
            mma_bf16(acc[m], ahf, bl[k][0], bl[k][1]);
            mma_bf16(acc[m], alf, bh[k][0], bh[k][1]);
        }
    }
}
#define ZERO_ACC8(acc) \
    _Pragma("unroll") for (int m = 0; m < 8; m++) \
    _Pragma("unroll") for (int q = 0; q < 4; q++) acc[m][q] = 0.f;

// ---------------- m1/m2 dual-output GEMM -------------------------------------
__global__ void __launch_bounds__(512, 1)
node_mma_m12(const float* __restrict__ A) {
    extern __shared__ char smc[];
    char* A_hi = smc + NM_A_HI;
    char* A_lo = smc + NM_A_LO;
    const int tid = threadIdx.x;
    const int wid = tid >> 5, lane = tid & 31;
    const int m0 = blockIdx.x * 128;
    const uint32_t ah_base = smem_u32(A_hi), al_base = smem_u32(A_lo);

    stage_A512(A_hi, A_lo, A, m0, tid);
    __syncthreads();

    uint32_t bh[8][2], bl[8][2];
    float acc[8][4];
    for (int s = 0; s < 2; s++) {
        load_F8(bh, bl, g_F[s][0], g_F[s][1], wid, lane);
        ZERO_ACC8(acc);
        mma_all8(acc, ah_base, al_base, bh, bl, lane);
        float* C = s ? g_m2 : g_m1;
        int n = wid * 8 + (lane & 3) * 2;
#pragma unroll
        for (int m = 0; m < 8; m++) {
            int r0 = m0 + m * 16 + (lane >> 2);
            int r1 = r0 + 8;
            if (r0 < NN) *(float2*)&C[r0 * HH + n] = make_float2(acc[m][0], acc[m][1]);
            if (r1 < NN) *(float2*)&C[r1 * HH + n] = make_float2(acc[m][2], acc[m][3]);
        }
    }
}

// ---------------- fused t-GEMM + h-GEMM --------------------------------------
__global__ void __launch_bounds__(512, 1)
node_mma_th(const float* __restrict__ Ah, const float* __restrict__ Amacc,
            const float* __restrict__ nb1, const float* __restrict__ nb2,
            float* __restrict__ hdst) {
    extern __shared__ char smc[];
    char* A_hi = smc + NM_A_HI;
    char* A_lo = smc + NM_A_LO;
    float* bs  = (float*)(smc + NM_MISC);
    float* bs2 = bs + 128;
    const int tid = threadIdx.x;
    const int wid = tid >> 5, lane = tid & 31;
    const int m0 = blockIdx.x * 128;
    const uint32_t ah_base = smem_u32(A_hi), al_base = smem_u32(A_lo);

    if (tid < 128) { bs[tid] = nb1[tid]; bs2[tid] = g_bme[tid]; }

    uint32_t bh[8][2], bl[8][2];
    float acc[8][4];
    ZERO_ACC8(acc);

    stage_A512(A_hi, A_lo, Ah, m0, tid);
    __syncthreads();
    load_F8(bh, bl, g_F[2][0], g_F[2][1], wid, lane);
    mma_all8(acc, ah_base, al_base, bh, bl, lane);
    __syncthreads();
    stage_A512(A_hi, A_lo, Amacc, m0, tid);
    __syncthreads();
    load_F8(bh, bl, g_F[6][0], g_F[6][1], wid, lane);
    mma_all8(acc, ah_base, al_base, bh, bl, lane);
    __syncthreads();

    // write T = relu(acc + nb1 + cnt*bme) into A smem as hi/lo
    {
        int n = wid * 8 + (lane & 3) * 2;
#pragma unroll
        for (int m = 0; m < 8; m++) {
            int r0l = m * 16 + (lane >> 2);
            int r1l = r0l + 8;
            int r0 = m0 + r0l, r1 = m0 + r1l;
            float cm0 = (r0 < NN) ? (float)g_cnt[r0] : 0.f;
            float cm1 = (r1 < NN) ? (float)g_cnt[r1] : 0.f;
            float o0 = fmaxf(acc[m][0] + bs[n] + cm0 * bs2[n], 0.f);
            float o1 = fmaxf(acc[m][1] + bs[n + 1] + cm0 * bs2[n + 1], 0.f);
            float o2 = fmaxf(acc[m][2] + bs[n] + cm1 * bs2[n], 0.f);
            float o3 = fmaxf(acc[m][3] + bs[n + 1] + cm1 * bs2[n + 1], 0.f);
            uint32_t hv, lv;
            hilo2(o0, o1, hv, lv);
            *(uint32_t*)(A_hi + r0l * NM_ST + n * 2) = hv;
            *(uint32_t*)(A_lo + r0l * NM_ST + n * 2) = lv;
            hilo2(o2, o3, hv, lv);
            *(uint32_t*)(A_hi + r1l * NM_ST + n * 2) = hv;
            *(uint32_t*)(A_lo + r1l * NM_ST + n * 2) = lv;
        }
    }
    __syncthreads();

    load_F8(bh, bl, g_F[3][0], g_F[3][1], wid, lane);
    ZERO_ACC8(acc);
    mma_all8(acc, ah_base, al_base, bh, bl, lane);

    {
        int n = wid * 8 + (lane & 3) * 2;
        float b0 = __ldg(&nb2[n]), b1 = __ldg(&nb2[n + 1]);
#pragma unroll
        for (int m = 0; m < 8; m++) {
            int r0 = m0 + m * 16 + (lane >> 2);
            int r1 = r0 + 8;
            if (r0 < NN) {
                float2 rv = *(const float2*)&Ah[r0 * HH + n];
                *(float2*)&hdst[r0 * HH + n] =
                    make_float2(acc[m][0] + b0 + rv.x, acc[m][1] + b1 + rv.y);
            }
            if (r1 < NN) {
                float2 rv = *(const float2*)&Ah[r1 * HH + n];
                *(float2*)&hdst[r1 * HH + n] =
                    make_float2(acc[m][2] + b0 + rv.x, acc[m][3] + b1 + rv.y);
            }
        }
    }
}

// ---------------- fused vW1-GEMM + v epilogue --------------------------------
__global__ void __launch_bounds__(512, 1)
node_mma_v(const float* __restrict__ A, const float* __restrict__ vb1,
           const float* __restrict__ vW2, const float* __restrict__ vb2,
           float* __restrict__ outv) {
    extern __shared__ char smc[];
    char* A_hi = smc + NM_A_HI;
    char* A_lo = smc + NM_A_LO;
    float* bs = (float*)(smc + NM_MISC);
    float* w2 = bs + 128;
    float* vp = w2 + 256;
    const int tid = threadIdx.x;
    const int wid = tid >> 5, lane = tid & 31;
    const int m0 = blockIdx.x * 128;
    const uint32_t ah_base = smem_u32(A_hi), al_base = smem_u32(A_lo);

    if (tid < 128) bs[tid] = vb1[tid];
    if (tid < 256) { w2[tid] = vW2[tid]; vp[tid] = 0.f; }

    stage_A512(A_hi, A_lo, A, m0, tid);
    __syncthreads();

    uint32_t bh[8][2], bl[8][2];
    load_F8(bh, bl, g_F[4][0], g_F[4][1], wid, lane);
    float acc[8][4];
    ZERO_ACC8(acc);
    mma_all8(acc, ah_base, al_base, bh, bl, lane);

    {
        int n = wid * 8 + (lane & 3) * 2;
#pragma unroll
        for (int m = 0; m < 8; m++) {
            int r0l = m * 16 + (lane >> 2);
            int r1l = r0l + 8;
            float o0 = fmaxf(acc[m][0] + bs[n], 0.f);
            float o1 = fmaxf(acc[m][1] + bs[n + 1], 0.f);
            float o2 = fmaxf(acc[m][2] + bs[n], 0.f);
            float o3 = fmaxf(acc[m][3] + bs[n + 1], 0.f);
            float c00 = o0 * w2[n * 2 + 0] + o1 * w2[(n + 1) * 2 + 0];
            float c01 = o0 * w2[n * 2 + 1] + o1 * w2[(n + 1) * 2 + 1];
            float c10 = o2 * w2[n * 2 + 0] + o3 * w2[(n + 1) * 2 + 0];
            float c11 = o2 * w2[n * 2 + 1] + o3 * w2[(n + 1) * 2 + 1];
            c00 += __shfl_xor_sync(0xffffffffu, c00, 1);
            c00 += __shfl_xor_sync(0xffffffffu, c00, 2);
            c01 += __shfl_xor_sync(0xffffffffu, c01, 1);
            c01 += __shfl_xor_sync(0xffffffffu, c01, 2);
            c10 += __shfl_xor_sync(0xffffffffu, c10, 1);
            c10 += __shfl_xor_sync(0xffffffffu, c10, 2);
            c11 += __shfl_xor_sync(0xffffffffu, c11, 1);
            c11 += __shfl_xor_sync(0xffffffffu, c11, 2);
            if ((lane & 3) == 0) {
                atomicAdd(&vp[2 * r0l + 0], c00);
                atomicAdd(&vp[2 * r0l + 1], c01);
                atomicAdd(&vp[2 * r1l + 0], c10);
                atomicAdd(&vp[2 * r1l + 1], c11);
            }
        }
    }
    __syncthreads();
    if (tid < 128) {
        int row = m0 + tid;
        if (row < NN) {
            float d = fmaxf((float)g_cnt[row], 1.f);
            float v0 = vp[2 * tid] + vb2[0] + g_scat[2 * row] / d;
            float v1 = vp[2 * tid + 1] + vb2[1] + g_scat[2 * row + 1] / d;
            float n = fmaxf(sqrtf(v0 * v0 + v1 * v1), 1e-12f);
            outv[2 * row] = v0 / n;
            outv[2 * row + 1] = v1 / n;
        }
    }
}

// ---------------- macc gather: one warp per node (no atomics; R13 form) ------
__global__ void macc_gather_kernel(const float* __restrict__ x,
                                   const float* __restrict__ eW1,
                                   const float* __restrict__ eb1) {
    int warp = (blockIdx.x * blockDim.x + threadIdx.x) >> 5;
    int lane = threadIdx.x & 31;
    if (warp >= NN) return;
    int r = warp;
    int j = lane << 2;
    float4 m1v = *(const float4*)&g_m1[r * HH + j];
    float4 wd  = *(const float4*)&eW1[256 * HH + j];
    float4 b1  = *(const float4*)&eb1[j];
    float2 xr  = *(const float2*)&x[2 * r];
    float4 acc = make_float4(0.f, 0.f, 0.f, 0.f);
    int s = g_off[r], e = g_off[r + 1];
    for (int idx = s; idx < e; idx++) {
        int c = __ldg(&g_cols[idx]);
        float2 xc = *(const float2*)&x[2 * c];
        float dx = xr.x - xc.x, dy = xr.y - xc.y;
        float rd = dx * dx + dy * dy;
        float4 m2v = *(const float4*)&g_m2[c * HH + j];
        acc.x += fmaxf(m1v.x + m2v.x + rd * wd.x + b1.x, 0.f);
        acc.y += fmaxf(m1v.y + m2v.y + rd * wd.y + b1.y, 0.f);
        acc.z += fmaxf(m1v.z + m2v.z + rd * wd.z + b1.z, 0.f);
        acc.w += fmaxf(m1v.w + m2v.w + rd * wd.w + b1.w, 0.f);
    }
    *(float4*)&g_macc[r * HH + j] = acc;
}

// ---------------- coord kernel (layer 2, 256 threads; R13 form) --------------
#define EK2_ASTRIDE 272
#define EK2_A_HI 0
#define EK2_A_LO 34816
#define EK2_MISC 69632
#define EK2_SMEM (EK2_MISC + 5120)

__global__ void __launch_bounds__(256)
edge2_kernel(const float* __restrict__ x,
             const float* __restrict__ eW1, const float* __restrict__ eb1,
             const float* __restrict__ cW2, const float* __restrict__ cb2) {
    extern __shared__ char smc[];
    char* A_hi = smc + EK2_A_HI;
    char* A_lo = smc + EK2_A_LO;
    float* misc   = (float*)(smc + EK2_MISC);
    float* wd_s   = misc;
    float* b1_s   = misc + 128;
    float* bc_s   = misc + 256;
    float* cw2_s  = misc + 384;
    float* p2a_s  = misc + 512;
    float* p2b_s  = misc + 640;
    float* rd_s   = misc + 768;
    float* coordp = misc + 896;
    int* row_s = (int*)(misc + 1024);
    int* col_s = (int*)(misc + 1152);

    const int tid = threadIdx.x;
    const int wid = tid >> 5, lane = tid & 31;

    if (tid < 128) {
        wd_s[tid]  = eW1[256 * HH + tid];
        b1_s[tid]  = eb1[tid];
        bc_s[tid]  = g_bc[tid];
        cw2_s[tid] = cW2[tid];
        coordp[tid] = 0.f;
        int eg = blockIdx.x * 128 + tid;
        int r = g_rows[eg], c = g_cols[eg];
        row_s[tid] = r; col_s[tid] = c;
        float2 xr = *(const float2*)&x[2 * r];
        float2 xc = *(const float2*)&x[2 * c];
        float dx = xr.x - xc.x, dy = xr.y - xc.y;
        rd_s[tid]  = dx * dx + dy * dy;
        p2a_s[tid] = dx * dx - dy * dy;
        p2b_s[tid] = 2.f * dx * dy;
    }
    // B fragments from table (matrix 5 = Wc), 8-warp mapping (2 n-tiles/warp)
    uint32_t bh[2][8][2], bl[2][8][2];
#pragma unroll
    for (int nt = 0; nt < 2; nt++)
#pragma unroll
        for (int k = 0; k < 8; k++) {
            int cg = wid * 2 + nt;
            uint2 v = __ldg(&g_F[5][0][(cg * 8 + k) * 32 + lane]);
            bh[nt][k][0] = v.x; bh[nt][k][1] = v.y;
            uint2 u = __ldg(&g_F[5][1][(cg * 8 + k) * 32 + lane]);
            bl[nt][k][0] = u.x; bl[nt][k][1] = u.y;
        }
    __syncthreads();

    // phase 1: preact, write A tiles
#pragma unroll
    for (int s = 0; s < 16; s++) {
        int item = tid + s * 256;
        int e = item >> 5, j = (item & 31) << 2;
        int r = row_s[e], c = col_s[e];
        float rd = rd_s[e];
        float4 a  = *(const float4*)&g_m1[r * HH + j];
        float4 b  = *(const float4*)&g_m2[c * HH + j];
        float4 w  = *(const float4*)&wd_s[j];
        float4 bb = *(const float4*)&b1_s[j];
        float v0 = fmaxf(a.x + b.x + rd * w.x + bb.x, 0.f);
        float v1 = fmaxf(a.y + b.y + rd * w.y + bb.y, 0.f);
        float v2 = fmaxf(a.z + b.z + rd * w.z + bb.z, 0.f);
        float v3 = fmaxf(a.w + b.w + rd * w.w + bb.w, 0.f);
        uint2 hv, lv;
        hilo4(v0, v1, v2, v3, hv, lv);
        int off = e * EK2_ASTRIDE + j * 2;
        *(uint2*)(A_hi + off) = hv;
        *(uint2*)(A_lo + off) = lv;
    }
    __syncthreads();

    // phase 2: C = A @ Wc via mma, fused coord dot + scatter
    {
        uint32_t hbase = smem_u32(A_hi);
        uint32_t lbase = smem_u32(A_lo);
        int aroff = (lane & 15) * EK2_ASTRIDE + ((lane >> 4) & 1) * 16;
#pragma unroll
        for (int m = 0; m < 8; m++) {
            float acc[2][4];
#pragma unroll
            for (int nt = 0; nt < 2; nt++)
#pragma unroll
                for (int q = 0; q < 4; q++) acc[nt][q] = 0.f;
#pragma unroll
            for (int k = 0; k < 8; k++) {
                uint32_t a = (m * 16) * EK2_ASTRIDE + k * 32 + aroff;
                uint32_t ah[4], al[4];
                ldmx4(ah, hbase + a);
                ldmx4(al, lbase + a);
#pragma unroll
                for (int nt = 0; nt < 2; nt++) {
                    mma_bf16(acc[nt], ah, bh[nt][k][0], bh[nt][k][1]);
                    mma_bf16(acc[nt], ah, bl[nt][k][0], bl[nt][k][1]);
                    mma_bf16(acc[nt], al, bh[nt][k][0], bh[nt][k][1]);
                }
            }
            int r0 = m * 16 + (lane >> 2);
            float p0 = 0.f, p1 = 0.f;
#pragma unroll
            for (int nt = 0; nt < 2; nt++) {
                int n = wid * 16 + nt * 8 + (lane & 3) * 2;
                p0 += fmaxf(acc[nt][0] + bc_s[n], 0.f) * cw2_s[n]
                    + fmaxf(acc[nt][1] + bc_s[n + 1], 0.f) * cw2_s[n + 1];
                p1 += fmaxf(acc[nt][2] + bc_s[n], 0.f) * cw2_s[n]
                    + fmaxf(acc[nt][3] + bc_s[n + 1], 0.f) * cw2_s[n + 1];
            }
            p0 += __shfl_xor_sync(0xffffffffu, p0, 1);
            p0 += __shfl_xor_sync(0xffffffffu, p0, 2);
            p1 += __shfl_xor_sync(0xffffffffu, p1, 1);
            p1 += __shfl_xor_sync(0xffffffffu, p1, 2);
            if ((lane & 3) == 0) {
                atomicAdd(&coordp[r0], p0);
                atomicAdd(&coordp[r0 + 8], p1);
            }
        }
    }
    __syncthreads();
    if (tid < 128) {
        float csum = coordp[tid] + cb2[0];
        red_add_v2(&g_scat[2 * row_s[tid]], p2a_s[tid] * csum, p2b_s[tid] * csum);
    }
}

__global__ void copy_x_kernel(const float* __restrict__ x, float* __restrict__ outx) {
    int i = blockIdx.x * blockDim.x + threadIdx.x;
    if (i < NN * 2) outx[i] = x[i];
}

// ---------------- launcher ---------------------------------------------------
extern "C" void kernel_launch(void* const* d_in, const int* in_sizes, int n_in,
                              void* d_out, int out_size) {
    const float* h0   = (const float*)d_in[0];
    const float* x    = (const float*)d_in[1];
    const int*   ei   = (const int*)d_in[2];
    const float* embW = (const float*)d_in[3];
    const float* embB = (const float*)d_in[4];
    const float* eW1  = (const float*)d_in[5];
    const float* eb1  = (const float*)d_in[6];
    const float* eW2  = (const float*)d_in[7];
    const float* eb2  = (const float*)d_in[8];
    const float* nW1  = (const float*)d_in[9];
    const float* nb1  = (const float*)d_in[10];
    const float* nW2  = (const float*)d_in[11];
    const float* nb2  = (const float*)d_in[12];
    const float* vW1  = (const float*)d_in[13];
    const float* vb1  = (const float*)d_in[14];
    const float* vW2  = (const float*)d_in[15];
    const float* vb2  = (const float*)d_in[16];
    const float* cW1  = (const float*)d_in[17];
    const float* cb1  = (const float*)d_in[18];
    const float* cW2  = (const float*)d_in[19];
    const float* cb2  = (const float*)d_in[20];

    float* out   = (float*)d_out;
    float* out_h = out;
    float* out_x = out + NN * HH;
    float* out_v = out + NN * HH + NN * 2;

    float *p_h, *p_macc;
    cudaGetSymbolAddress((void**)&p_h,    g_h);
    cudaGetSymbolAddress((void**)&p_macc, g_macc);

    cudaFuncSetAttribute(node_mma_m12, cudaFuncAttributeMaxDynamicSharedMemorySize, NM_SMEM);
    cudaFuncSetAttribute(node_mma_th, cudaFuncAttributeMaxDynamicSharedMemorySize, NM_SMEM);
    cudaFuncSetAttribute(node_mma_v, cudaFuncAttributeMaxDynamicSharedMemorySize, NM_SMEM);
    cudaFuncSetAttribute(edge2_kernel, cudaFuncAttributeMaxDynamicSharedMemorySize, EK2_SMEM);
    cudaFuncSetAttribute(prep_frag_kernel, cudaFuncAttributeMaxDynamicSharedMemorySize, 69632);

    const int GB = (NN + 127) / 128;

    // side streams + events, created fresh every call and destroyed before return
    cudaStream_t s1, s2;
    cudaStreamCreateWithFlags(&s1, cudaStreamNonBlocking);
    cudaStreamCreateWithFlags(&s2, cudaStreamNonBlocking);
    cudaEvent_t eFork, eSort, eFork2, eEdge, eEmb;
    cudaEventCreateWithFlags(&eFork,  cudaEventDisableTiming);
    cudaEventCreateWithFlags(&eSort,  cudaEventDisableTiming);
    cudaEventCreateWithFlags(&eFork2, cudaEventDisableTiming);
    cudaEventCreateWithFlags(&eEdge,  cudaEventDisableTiming);
    cudaEventCreateWithFlags(&eEmb,   cudaEventDisableTiming);

    cudaEventRecord(eFork, 0);

    // --- branch s1: sort pipeline ---
    cudaStreamWaitEvent(s1, eFork, 0);
    zero_cnt_scat_kernel<<<(NN * 2 + 255) / 256, 256, 0, s1>>>();
    count_kernel<<<(EE + 255) / 256, 256, 0, s1>>>(ei);
    scan1_kernel<<<SCAN_B, 256, 0, s1>>>();
    scan2_kernel<<<1, 256, 0, s1>>>();
    scan3_kernel<<<SCAN_B, 256, 0, s1>>>();
    scatter_kernel<<<(EE + 255) / 256, 256, 0, s1>>>(ei);
    cudaEventRecord(eSort, s1);

    // --- branch s2: copy x out + embed (input-only dependencies) ---
    cudaStreamWaitEvent(s2, eFork, 0);
    copy_x_kernel<<<(NN * 2 + 255) / 256, 256, 0, s2>>>(x, out_x);
    embed_kernel<<<NN / 2, 256, 0, s2>>>(h0, embW, embB);
    cudaEventRecord(eEmb, s2);

    // --- main: weight prep (transpose, then fragment tables) ---
    {
        dim3 g(128, 7);
        prep_all_kernel<<<g, 128>>>(eW1, nW1, nW2, vW1, eW2, cW1, eb2, cb1);
    }
    prep_frag_kernel<<<7, 256, 69632>>>();

    // ---- layer 0 ----
    cudaStreamWaitEvent(0, eEmb, 0);
    node_mma_m12<<<GB, 512, NM_SMEM>>>(p_h);
    cudaStreamWaitEvent(0, eSort, 0);
    macc_gather_kernel<<<(NN * 32 + 255) / 256, 256>>>(x, eW1, eb1);
    node_mma_th<<<GB, 512, NM_SMEM>>>(p_h, p_macc, nb1, nb2, p_h);

    // ---- layer 1 ----
    node_mma_m12<<<GB, 512, NM_SMEM>>>(p_h);
    cudaEventRecord(eFork2, 0);
    cudaStreamWaitEvent(s1, eFork2, 0);
    edge2_kernel<<<EE / 128, 256, EK2_SMEM, s1>>>(x, eW1, eb1, cW2, cb2);
    cudaEventRecord(eEdge, s1);
    macc_gather_kernel<<<(NN * 32 + 255) / 256, 256>>>(x, eW1, eb1);
    node_mma_th<<<GB, 512, NM_SMEM>>>(p_h, p_macc, nb1, nb2, out_h);

    // join: v epilogue needs edge2's g_scat and th's out_h
    cudaStreamWaitEvent(0, eEdge, 0);
    node_mma_v<<<GB, 512, NM_SMEM>>>(out_h, vb1, vW2, vb2, out_v);

    // cleanup (allocation guard: return device memory to baseline)
    cudaEventDestroy(eFork);
    cudaEventDestroy(eSort);
    cudaEventDestroy(eFork2);
    cudaEventDestroy(eEdge);
    cudaEventDestroy(eEmb);
    cudaStreamDestroy(s1);
    cudaStreamDestroy(s2);
}

// round 16
// speedup vs baseline: 1.0877x; 1.0025x over previous
#include <cuda_runtime.h>
#include <cuda_bf16.h>
#include <cstdint>

#define NN 50000
#define EE 800000
#define HH 128
#define PP 16
#define SCAN_B 196   // ceil(NN/256)

typedef __nv_bfloat16 bf16;

// ---------------- scratch (device globals; no allocation allowed) -----------
__device__ float g_h[NN * HH];
__device__ float g_m1[NN * HH];
__device__ float g_m2[NN * HH];
__device__ float g_macc[NN * HH];
__device__ float g_scat[NN * 2];
__device__ int   g_cnt[NN];
__device__ int   g_off[NN + 1];
__device__ int   g_cur[NN];
__device__ int   g_bsum[SCAN_B];
__device__ int   g_rows[EE];
__device__ int   g_cols[EE];
__device__ float g_bc[HH];
__device__ float g_bme[HH];
// transposed bf16 hi/lo weights: B[n][k] = W[k][n]
__device__ bf16 g_Bhi[HH * HH];      // Wc (coord)
__device__ bf16 g_Blo[HH * HH];
__device__ bf16 g_BeW1a_h[HH * HH], g_BeW1a_l[HH * HH];
__device__ bf16 g_BeW1b_h[HH * HH], g_BeW1b_l[HH * HH];
__device__ bf16 g_BnW1a_h[HH * HH], g_BnW1a_l[HH * HH];
__device__ bf16 g_BnW2_h[HH * HH],  g_BnW2_l[HH * HH];
__device__ bf16 g_BvW1_h[HH * HH],  g_BvW1_l[HH * HH];
__device__ bf16 g_BWme_h[HH * HH],  g_BWme_l[HH * HH];
// B fragment tables: [matrix][hi/lo][ (cg*8+k)*32 + lane ], cg = colgroup (n/8)
// matrices: 0 eW1a, 1 eW1b, 2 nW1a, 3 nW2, 4 vW1, 5 Wc, 6 Wme
__device__ uint2 g_F[7][2][4096];

// ---------------- PTX helpers ------------------------------------------------
__device__ __forceinline__ void red_add_v2(float* p, float a, float b) {
    asm volatile("red.global.add.v2.f32 [%0], {%1,%2};"
                 :: "l"(p), "f"(a), "f"(b) : "memory");
}
__device__ __forceinline__ uint32_t smem_u32(const void* p) {
    uint32_t a;
    asm("{ .reg .u64 t; cvta.to.shared.u64 t, %1; cvt.u32.u64 %0, t; }" : "=r"(a) : "l"(p));
    return a;
}
__device__ __forceinline__ void ldmx4(uint32_t* r, uint32_t a) {
    asm volatile("ldmatrix.sync.aligned.m8n8.x4.shared.b16 {%0,%1,%2,%3}, [%4];"
                 : "=r"(r[0]), "=r"(r[1]), "=r"(r[2]), "=r"(r[3]) : "r"(a));
}
__device__ __forceinline__ void ldmx2(uint32_t& r0, uint32_t& r1, uint32_t a) {
    asm volatile("ldmatrix.sync.aligned.m8n8.x2.shared.b16 {%0,%1}, [%2];"
                 : "=r"(r0), "=r"(r1) : "r"(a));
}
__device__ __forceinline__ void mma_bf16(float* c, const uint32_t* a, uint32_t b0, uint32_t b1) {
    asm volatile(
        "mma.sync.aligned.m16n8k16.row.col.f32.bf16.bf16.f32 "
        "{%0,%1,%2,%3}, {%4,%5,%6,%7}, {%8,%9}, {%0,%1,%2,%3};"
        : "+f"(c[0]), "+f"(c[1]), "+f"(c[2]), "+f"(c[3])
        : "r"(a[0]), "r"(a[1]), "r"(a[2]), "r"(a[3]), "r"(b0), "r"(b1));
}
__device__ __forceinline__ void hilo4(float v0, float v1, float v2, float v3,
                                      uint2& hv, uint2& lv) {
    bf16 h0 = __float2bfloat16(v0), h1 = __float2bfloat16(v1);
    bf16 h2 = __float2bfloat16(v2), h3 = __float2bfloat16(v3);
    bf16 l0 = __float2bfloat16(v0 - __bfloat162float(h0));
    bf16 l1 = __float2bfloat16(v1 - __bfloat162float(h1));
    bf16 l2 = __float2bfloat16(v2 - __bfloat162float(h2));
    bf16 l3 = __float2bfloat16(v3 - __bfloat162float(h3));
    hv.x = ((uint32_t)__bfloat16_as_ushort(h1) << 16) | __bfloat16_as_ushort(h0);
    hv.y = ((uint32_t)__bfloat16_as_ushort(h3) << 16) | __bfloat16_as_ushort(h2);
    lv.x = ((uint32_t)__bfloat16_as_ushort(l1) << 16) | __bfloat16_as_ushort(l0);
    lv.y = ((uint32_t)__bfloat16_as_ushort(l3) << 16) | __bfloat16_as_ushort(l2);
}
__device__ __forceinline__ void hilo2(float a, float b, uint32_t& h, uint32_t& l) {
    bf16 ha = __float2bfloat16(a), hb = __float2bfloat16(b);
    bf16 la = __float2bfloat16(a - __bfloat162float(ha));
    bf16 lb = __float2bfloat16(b - __bfloat162float(hb));
    h = ((uint32_t)__bfloat16_as_ushort(hb) << 16) | __bfloat16_as_ushort(ha);
    l = ((uint32_t)__bfloat16_as_ushort(lb) << 16) | __bfloat16_as_ushort(la);
}

// ---------------- sort pipeline ----------------------------------------------
__global__ void zero_cnt_scat_kernel() {
    int i = blockIdx.x * blockDim.x + threadIdx.x;
    if (i < NN) g_cnt[i] = 0;
    if (i < NN * 2) g_scat[i] = 0.f;
}

__global__ void count_kernel(const int* __restrict__ ei) {
    int e = blockIdx.x * blockDim.x + threadIdx.x;
    if (e < EE) atomicAdd(&g_cnt[ei[e]], 1);
}

__global__ void scan1_kernel() {
    __shared__ int sm[256];
    int b = blockIdx.x, t = threadIdx.x, i = b * 256 + t;
    int v = (i < NN) ? g_cnt[i] : 0;
    sm[t] = v; __syncthreads();
    for (int o = 128; o; o >>= 1) {
        if (t < o) sm[t] += sm[t + o];
        __syncthreads();
    }
    if (t == 0) g_bsum[b] = sm[0];
}

__global__ void scan2_kernel() {
    __shared__ int sm[256];
    int t = threadIdx.x;
    int v = (t < SCAN_B) ? g_bsum[t] : 0;
    sm[t] = v; __syncthreads();
    for (int o = 1; o < 256; o <<= 1) {
        int add = (t >= o) ? sm[t - o] : 0;
        __syncthreads();
        sm[t] += add;
        __syncthreads();
    }
    if (t < SCAN_B) g_bsum[t] = sm[t] - v;
    if (t == 0) g_off[NN] = EE;
}

__global__ void scan3_kernel() {
    __shared__ int sm[256];
    int b = blockIdx.x, t = threadIdx.x, i = b * 256 + t;
    int v = (i < NN) ? g_cnt[i] : 0;
    sm[t] = v; __syncthreads();
    for (int o = 1; o < 256; o <<= 1) {
        int add = (t >= o) ? sm[t - o] : 0;
        __syncthreads();
        sm[t] += add;
        __syncthreads();
    }
    if (i < NN) {
        int off = g_bsum[b] + sm[t] - v;
        g_off[i] = off;
        g_cur[i] = off;
    }
}

__global__ void scatter_kernel(const int* __restrict__ ei) {
    int e = blockIdx.x * blockDim.x + threadIdx.x;
    if (e < EE) {
        int r = ei[e];
        int pos = atomicAdd(&g_cur[r], 1);
        g_rows[pos] = r;
        g_cols[pos] = ei[EE + e];
    }
}

// ---------------- weight prep -------------------------------------------------
__global__ void prep_all_kernel(const float* __restrict__ eW1, const float* __restrict__ nW1,
                                const float* __restrict__ nW2, const float* __restrict__ vW1,
                                const float* __restrict__ eW2, const float* __restrict__ cW1,
                                const float* __restrict__ eb2, const float* __restrict__ cb1) {
    int i = blockIdx.x, j = threadIdx.x;
    int task = blockIdx.y;
    if (task < 5) {
        const float* W;
        bf16 *oh, *ol;
        switch (task) {
            case 0: W = eW1;            oh = g_BeW1a_h; ol = g_BeW1a_l; break;
            case 1: W = eW1 + 128 * HH; oh = g_BeW1b_h; ol = g_BeW1b_l; break;
            case 2: W = nW1;            oh = g_BnW1a_h; ol = g_BnW1a_l; break;
            case 3: W = nW2;            oh = g_BnW2_h;  ol = g_BnW2_l;  break;
            default: W = vW1;           oh = g_BvW1_h;  ol = g_BvW1_l;  break;
        }
        float s = W[i * HH + j];
        bf16 hi = __float2bfloat16(s);
        bf16 lo = __float2bfloat16(s - __bfloat162float(hi));
        oh[j * HH + i] = hi;
        ol[j * HH + i] = lo;
    } else if (task == 5) {
        float s = 0.f;
        for (int k = 0; k < HH; k++) s += eW2[i * HH + k] * cW1[k * HH + j];
        bf16 hi = __float2bfloat16(s);
        bf16 lo = __float2bfloat16(s - __bfloat162float(hi));
        g_Bhi[j * HH + i] = hi;
        g_Blo[j * HH + i] = lo;
        if (i == 0) {
            float t = 0.f;
            for (int k = 0; k < HH; k++) t += eb2[k] * cW1[k * HH + j];
            g_bc[j] = t + cb1[j];
        }
    } else {
        const float* nW1b = nW1 + 128 * HH;
        float s = 0.f;
        for (int k = 0; k < HH; k++) s += eW2[i * HH + k] * nW1b[k * HH + j];
        bf16 hi = __float2bfloat16(s);
        bf16 lo = __float2bfloat16(s - __bfloat162float(hi));
        g_BWme_h[j * HH + i] = hi;
        g_BWme_l[j * HH + i] = lo;
        if (i == 0) {
            float t = 0.f;
            for (int k = 0; k < HH; k++) t += eb2[k] * nW1b[k * HH + j];
            g_bme[j] = t;
        }
    }
}

#define NM_ST 272
__global__ void prep_frag_kernel() {
    extern __shared__ char smc[];
    char* S_hi = smc;
    char* S_lo = smc + 34816;
    int task = blockIdx.x, tid = threadIdx.x, wid = tid >> 5, lane = tid & 31;
    const bf16 *Bh, *Bl;
    switch (task) {
        case 0: Bh = g_BeW1a_h; Bl = g_BeW1a_l; break;
        case 1: Bh = g_BeW1b_h; Bl = g_BeW1b_l; break;
        case 2: Bh = g_BnW1a_h; Bl = g_BnW1a_l; break;
        case 3: Bh = g_BnW2_h;  Bl = g_BnW2_l;  break;
        case 4: Bh = g_BvW1_h;  Bl = g_BvW1_l;  break;
        case 5: Bh = g_Bhi;     Bl = g_Blo;     break;
        default: Bh = g_BWme_h; Bl = g_BWme_l;  break;
    }
    for (int idx = tid; idx < 8192; idx += 256) {
        int n = idx >> 6, kp = idx & 63;
        int off = n * NM_ST + kp * 4;
        *(uint32_t*)(S_hi + off) = ((const uint32_t*)Bh)[idx];
        *(uint32_t*)(S_lo + off) = ((const uint32_t*)Bl)[idx];
    }
    __syncthreads();
    uint32_t hbase = smem_u32(S_hi), lbase = smem_u32(S_lo);
    int roff = (lane & 7) * NM_ST + ((lane >> 3) & 1) * 16;
#pragma unroll
    for (int nt = 0; nt < 2; nt++)
#pragma unroll
        for (int k = 0; k < 8; k++) {
            uint32_t a = (wid * 16 + nt * 8) * NM_ST + k * 32 + roff;
            uint32_t h0, h1, l0, l1;
            ldmx2(h0, h1, hbase + a);
            ldmx2(l0, l1, lbase + a);
            int cg = wid * 2 + nt;
            g_F[task][0][(cg * 8 + k) * 32 + lane] = make_uint2(h0, h1);
            g_F[task][1][(cg * 8 + k) * 32 + lane] = make_uint2(l0, l1);
        }
}

__global__ void embed_kernel(const float* __restrict__ h0, const float* __restrict__ W,
                             const float* __restrict__ b) {
    int row = blockIdx.x * 2 + (threadIdx.x >> 7);
    int j = threadIdx.x & 127;
    if (row >= NN) return;
    float s = b[j];
#pragma unroll
    for (int k = 0; k < PP; k++) s += h0[row * PP + k] * W[k * HH + j];
    g_h[row * HH + j] = s;
}

// ---------------- 512-thread node MMA machinery -------------------------------
#define NM_A_HI 0
#define NM_A_LO 34816
#define NM_MISC 69632
#define NM_SMEM (NM_MISC + 4096)

__device__ __forceinline__ void stage_A512(char* A_hi, char* A_lo, const float* A,
                                           int m0, int tid) {
    for (int idx = tid; idx < 128 * 32; idx += 512) {
        int r = idx >> 5, c4 = (idx & 31) << 2;
        int gr = m0 + r;
        float4 v = (gr < NN) ? *(const float4*)&A[gr * HH + c4]
                             : make_float4(0.f, 0.f, 0.f, 0.f);
        uint2 hv, lv;
        hilo4(v.x, v.y, v.z, v.w, hv, lv);
        int off = r * NM_ST + c4 * 2;
        *(uint2*)(A_hi + off) = hv;
        *(uint2*)(A_lo + off) = lv;
    }
}
__device__ __forceinline__ void load_F8(uint32_t bh[8][2], uint32_t bl[8][2],
                                        const uint2* Fh, const uint2* Fl,
                                        int wid, int lane) {
#pragma unroll
    for (int k = 0; k < 8; k++) {
        uint2 v = __ldg(&Fh[(wid * 8 + k) * 32 + lane]);
        bh[k][0] = v.x; bh[k][1] = v.y;
        uint2 u = __ldg(&Fl[(wid * 8 + k) * 32 + lane]);
        bl[k][0] = u.x; bl[k][1] = u.y;
    }
}
__device__ __forceinline__ void mma_all8(float acc[8][4], uint32_t ah_base, uint32_t al_base,
                                         uint32_t bh[8][2], uint32_t bl[8][2], int lane) {
    int aroff = (lane & 15) * NM_ST + ((lane >> 4) & 1) * 16;
#pragma unroll
    for (int m = 0; m < 8; m++) {
#pragma unroll
        for (int k = 0; k < 8; k++) {
            uint32_t a = (m * 16) * NM_ST + k * 32 + aroff;
            uint32_t ahf[4], alf[4];
            ldmx4(ahf, ah_base + a);
            ldmx4(alf, al_base + a);
            mma_bf16(acc[m], ahf, bh[k][0], bh[k][1]);
            mma_bf16(acc[m], ahf, bl[k][0], bl[k][1]);
            mma_bf16(acc[m], alf, bh[k][0], bh[k][1]);
        }
    }
}
#define ZERO_ACC8(acc) \
    _Pragma("unroll") for (int m = 0; m < 8; m++) \
    _Pragma("unroll") for (int q = 0; q < 4; q++) acc[m][q] = 0.f;

// ---------------- m1/m2 dual-output GEMM (layer 0 only) -----------------------
__global__ void __launch_bounds__(512, 1)
node_mma_m12(const float* __restrict__ A) {
    extern __shared__ char smc[];
    char* A_hi = smc + NM_A_HI;
    char* A_lo = smc + NM_A_LO;
    const int tid = threadIdx.x;
    const int wid = tid >> 5, lane = tid & 31;
    const int m0 = blockIdx.x * 128;
    const uint32_t ah_base = smem_u32(A_hi), al_base = smem_u32(A_lo);

    stage_A512(A_hi, A_lo, A, m0, tid);
    __syncthreads();

    uint32_t bh[8][2], bl[8][2];
    float acc[8][4];
    for (int s = 0; s < 2; s++) {
        load_F8(bh, bl, g_F[s][0], g_F[s][1], wid, lane);
        ZERO_ACC8(acc);
        mma_all8(acc, ah_base, al_base, bh, bl, lane);
        float* C = s ? g_m2 : g_m1;
        int n = wid * 8 + (lane & 3) * 2;
#pragma unroll
        for (int m = 0; m < 8; m++) {
            int r0 = m0 + m * 16 + (lane >> 2);
            int r1 = r0 + 8;
            if (r0 < NN) *(float2*)&C[r0 * HH + n] = make_float2(acc[m][0], acc[m][1]);
            if (r1 < NN) *(float2*)&C[r1 * HH + n] = make_float2(acc[m][2], acc[m][3]);
        }
    }
}

// ---------------- fused t-GEMM + h-GEMM (+ optional m12 of next layer) --------
__global__ void __launch_bounds__(512, 1)
node_mma_th(const float* __restrict__ Ah, const float* __restrict__ Amacc,
            const float* __restrict__ nb1, const float* __restrict__ nb2,
            float* __restrict__ hdst, int do_m12) {
    extern __shared__ char smc[];
    char* A_hi = smc + NM_A_HI;
    char* A_lo = smc + NM_A_LO;
    float* bs  = (float*)(smc + NM_MISC);
    float* bs2 = bs + 128;
    const int tid = threadIdx.x;
    const int wid = tid >> 5, lane = tid & 31;
    const int m0 = blockIdx.x * 128;
    const uint32_t ah_base = smem_u32(A_hi), al_base = smem_u32(A_lo);

    if (tid < 128) { bs[tid] = nb1[tid]; bs2[tid] = g_bme[tid]; }

    uint32_t bh[8][2], bl[8][2];
    float acc[8][4];
    ZERO_ACC8(acc);

    stage_A512(A_hi, A_lo, Ah, m0, tid);
    __syncthreads();
    load_F8(bh, bl, g_F[2][0], g_F[2][1], wid, lane);
    mma_all8(acc, ah_base, al_base, bh, bl, lane);
    __syncthreads();
    stage_A512(A_hi, A_lo, Amacc, m0, tid);
    __syncthreads();
    load_F8(bh, bl, g_F[6][0], g_F[6][1], wid, lane);
    mma_all8(acc, ah_base, al_base, bh, bl, lane);
    __syncthreads();

    // write T = relu(acc + nb1 + cnt*bme) into A smem as hi/lo
    {
        int n = wid * 8 + (lane & 3) * 2;
#pragma unroll
        for (int m = 0; m < 8; m++) {
            int r0l = m * 16 + (lane >> 2);
            int r1l = r0l + 8;
            int r0 = m0 + r0l, r1 = m0 + r1l;
            float cm0 = (r0 < NN) ? (float)g_cnt[r0] : 0.f;
            float cm1 = (r1 < NN) ? (float)g_cnt[r1] : 0.f;
            float o0 = fmaxf(acc[m][0] + bs[n] + cm0 * bs2[n], 0.f);
            float o1 = fmaxf(acc[m][1] + bs[n + 1] + cm0 * bs2[n + 1], 0.f);
            float o2 = fmaxf(acc[m][2] + bs[n] + cm1 * bs2[n], 0.f);
            float o3 = fmaxf(acc[m][3] + bs[n + 1] + cm1 * bs2[n + 1], 0.f);
            uint32_t hv, lv;
            hilo2(o0, o1, hv, lv);
            *(uint32_t*)(A_hi + r0l * NM_ST + n * 2) = hv;
            *(uint32_t*)(A_lo + r0l * NM_ST + n * 2) = lv;
            hilo2(o2, o3, hv, lv);
            *(uint32_t*)(A_hi + r1l * NM_ST + n * 2) = hv;
            *(uint32_t*)(A_lo + r1l * NM_ST + n * 2) = lv;
        }
    }
    __syncthreads();

    // phase B: h_new = h + T @ nW2 + nb2
    load_F8(bh, bl, g_F[3][0], g_F[3][1], wid, lane);
    ZERO_ACC8(acc);
    mma_all8(acc, ah_base, al_base, bh, bl, lane);
    __syncthreads();   // all warps done reading T before overwriting A smem

    {
        int n = wid * 8 + (lane & 3) * 2;
        float b0 = __ldg(&nb2[n]), b1 = __ldg(&nb2[n + 1]);
#pragma unroll
        for (int m = 0; m < 8; m++) {
            int r0l = m * 16 + (lane >> 2);
            int r1l = r0l + 8;
            int r0 = m0 + r0l, r1 = m0 + r1l;
            float o0 = 0.f, o1 = 0.f, o2 = 0.f, o3 = 0.f;
            if (r0 < NN) {
                float2 rv = *(const float2*)&Ah[r0 * HH + n];
                o0 = acc[m][0] + b0 + rv.x;
                o1 = acc[m][1] + b1 + rv.y;
                *(float2*)&hdst[r0 * HH + n] = make_float2(o0, o1);
            }
            if (r1 < NN) {
                float2 rv = *(const float2*)&Ah[r1 * HH + n];
                o2 = acc[m][2] + b0 + rv.x;
                o3 = acc[m][3] + b1 + rv.y;
                *(float2*)&hdst[r1 * HH + n] = make_float2(o2, o3);
            }
            if (do_m12) {
                uint32_t hv, lv;
                hilo2(o0, o1, hv, lv);
                *(uint32_t*)(A_hi + r0l * NM_ST + n * 2) = hv;
                *(uint32_t*)(A_lo + r0l * NM_ST + n * 2) = lv;
                hilo2(o2, o3, hv, lv);
                *(uint32_t*)(A_hi + r1l * NM_ST + n * 2) = hv;
                *(uint32_t*)(A_lo + r1l * NM_ST + n * 2) = lv;
            }
        }
    }

    // phase C: m1/m2 of the next layer from h_new (block-local, no re-read)
    if (do_m12) {
        __syncthreads();
        for (int s = 0; s < 2; s++) {
            load_F8(bh, bl, g_F[s][0], g_F[s][1], wid, lane);
            ZERO_ACC8(acc);
            mma_all8(acc, ah_base, al_base, bh, bl, lane);
            float* C = s ? g_m2 : g_m1;
            int n = wid * 8 + (lane & 3) * 2;
#pragma unroll
            for (int m = 0; m < 8; m++) {
                int r0 = m0 + m * 16 + (lane >> 2);
                int r1 = r0 + 8;
                if (r0 < NN) *(float2*)&C[r0 * HH + n] = make_float2(acc[m][0], acc[m][1]);
                if (r1 < NN) *(float2*)&C[r1 * HH + n] = make_float2(acc[m][2], acc[m][3]);
            }
        }
    }
}

// ---------------- fused vW1-GEMM + v epilogue --------------------------------
__global__ void __launch_bounds__(512, 1)
node_mma_v(const float* __restrict__ A, const float* __restrict__ vb1,
           const float* __restrict__ vW2, const float* __restrict__ vb2,
           float* __restrict__ outv) {
    extern __shared__ char smc[];
    char* A_hi = smc + NM_A_HI;
    char* A_lo = smc + NM_A_LO;
    float* bs = (float*)(smc + NM_MISC);
    float* w2 = bs + 128;
    float* vp = w2 + 256;
    const int tid = threadIdx.x;
    const int wid = tid >> 5, lane = tid & 31;
    const int m0 = blockIdx.x * 128;
    const uint32_t ah_base = smem_u32(A_hi), al_base = smem_u32(A_lo);

    if (tid < 128) bs[tid] = vb1[tid];
    if (tid < 256) { w2[tid] = vW2[tid]; vp[tid] = 0.f; }

    stage_A512(A_hi, A_lo, A, m0, tid);
    __syncthreads();

    uint32_t bh[8][2], bl[8][2];
    load_F8(bh, bl, g_F[4][0], g_F[4][1], wid, lane);
    float acc[8][4];
    ZERO_ACC8(acc);
    mma_all8(acc, ah_base, al_base, bh, bl, lane);

    {
        int n = wid * 8 + (lane & 3) * 2;
#pragma unroll
        for (int m = 0; m < 8; m++) {
            int r0l = m * 16 + (lane >> 2);
            int r1l = r0l + 8;
            float o0 = fmaxf(acc[m][0] + bs[n], 0.f);
            float o1 = fmaxf(acc[m][1] + bs[n + 1], 0.f);
            float o2 = fmaxf(acc[m][2] + bs[n], 0.f);
            float o3 = fmaxf(acc[m][3] + bs[n + 1], 0.f);
            float c00 = o0 * w2[n * 2 + 0] + o1 * w2[(n + 1) * 2 + 0];
            float c01 = o0 * w2[n * 2 + 1] + o1 * w2[(n + 1) * 2 + 1];
            float c10 = o2 * w2[n * 2 + 0] + o3 * w2[(n + 1) * 2 + 0];
            float c11 = o2 * w2[n * 2 + 1] + o3 * w2[(n + 1) * 2 + 1];
            c00 += __shfl_xor_sync(0xffffffffu, c00, 1);
            c00 += __shfl_xor_sync(0xffffffffu, c00, 2);
            c01 += __shfl_xor_sync(0xffffffffu, c01, 1);
            c01 += __shfl_xor_sync(0xffffffffu, c01, 2);
            c10 += __shfl_xor_sync(0xffffffffu, c10, 1);
            c10 += __shfl_xor_sync(0xffffffffu, c10, 2);
            c11 += __shfl_xor_sync(0xffffffffu, c11, 1);
            c11 += __shfl_xor_sync(0xffffffffu, c11, 2);
            if ((lane & 3) == 0) {
                atomicAdd(&vp[2 * r0l + 0], c00);
                atomicAdd(&vp[2 * r0l + 1], c01);
                atomicAdd(&vp[2 * r1l + 0], c10);
                atomicAdd(&vp[2 * r1l + 1], c11);
            }
        }
    }
    __syncthreads();
    if (tid < 128) {
        int row = m0 + tid;
        if (row < NN) {
            float d = fmaxf((float)g_cnt[row], 1.f);
            float v0 = vp[2 * tid] + vb2[0] + g_scat[2 * row] / d;
            float v1 = vp[2 * tid + 1] + vb2[1] + g_scat[2 * row + 1] / d;
            float n = fmaxf(sqrtf(v0 * v0 + v1 * v1), 1e-12f);
            outv[2 * row] = v0 / n;
            outv[2 * row + 1] = v1 / n;
        }
    }
}

// ---------------- macc gather: one warp per node (no atomics) ----------------
__global__ void macc_gather_kernel(const float* __restrict__ x,
                                   const float* __restrict__ eW1,
                                   const float* __restrict__ eb1) {
    int warp = (blockIdx.x * blockDim.x + threadIdx.x) >> 5;
    int lane = threadIdx.x & 31;
    if (warp >= NN) return;
    int r = warp;
    int j = lane << 2;
    float4 m1v = *(const float4*)&g_m1[r * HH + j];
    float4 wd  = *(const float4*)&eW1[256 * HH + j];
    float4 b1  = *(const float4*)&eb1[j];
    float2 xr  = *(const float2*)&x[2 * r];
    float4 acc = make_float4(0.f, 0.f, 0.f, 0.f);
    int s = g_off[r], e = g_off[r + 1];
    for (int idx = s; idx < e; idx++) {
        int c = __ldg(&g_cols[idx]);
        float2 xc = *(const float2*)&x[2 * c];
        float dx = xr.x - xc.x, dy = xr.y - xc.y;
        float rd = dx * dx + dy * dy;
        float4 m2v = *(const float4*)&g_m2[c * HH + j];
        acc.x += fmaxf(m1v.x + m2v.x + rd * wd.x + b1.x, 0.f);
        acc.y += fmaxf(m1v.y + m2v.y + rd * wd.y + b1.y, 0.f);
        acc.z += fmaxf(m1v.z + m2v.z + rd * wd.z + b1.z, 0.f);
        acc.w += fmaxf(m1v.w + m2v.w + rd * wd.w + b1.w, 0.f);
    }
    *(float4*)&g_macc[r * HH + j] = acc;
}

// ---------------- coord kernel (layer 2, 256 threads) ------------------------
#define EK2_ASTRIDE 272
#define EK2_A_HI 0
#define EK2_A_LO 34816
#define EK2_MISC 69632
#define EK2_SMEM (EK2_MISC + 5120)

__global__ void __launch_bounds__(256)
edge2_kernel(const float* __restrict__ x,
             const float* __restrict__ eW1, const float* __restrict__ eb1,
             const float* __restrict__ cW2, const float* __restrict__ cb2) {
    extern __shared__ char smc[];
    char* A_hi = smc + EK2_A_HI;
    char* A_lo = smc + EK2_A_LO;
    float* misc   = (float*)(smc + EK2_MISC);
    float* wd_s   = misc;
    float* b1_s   = misc + 128;
    float* bc_s   = misc + 256;
    float* cw2_s  = misc + 384;
    float* p2a_s  = misc + 512;
    float* p2b_s  = misc + 640;
    float* rd_s   = misc + 768;
    float* coordp = misc + 896;
    int* row_s = (int*)(misc + 1024);
    int* col_s = (int*)(misc + 1152);

    const int tid = threadIdx.x;
    const int wid = tid >> 5, lane = tid & 31;

    if (tid < 128) {
        wd_s[tid]  = eW1[256 * HH + tid];
        b1_s[tid]  = eb1[tid];
        bc_s[tid]  = g_bc[tid];
        cw2_s[tid] = cW2[tid];
        coordp[tid] = 0.f;
        int eg = blockIdx.x * 128 + tid;
        int r = g_rows[eg], c = g_cols[eg];
        row_s[tid] = r; col_s[tid] = c;
        float2 xr = *(const float2*)&x[2 * r];
        float2 xc = *(const float2*)&x[2 * c];
        float dx = xr.x - xc.x, dy = xr.y - xc.y;
        rd_s[tid]  = dx * dx + dy * dy;
        p2a_s[tid] = dx * dx - dy * dy;
        p2b_s[tid] = 2.f * dx * dy;
    }
    uint32_t bh[2][8][2], bl[2][8][2];
#pragma unroll
    for (int nt = 0; nt < 2; nt++)
#pragma unroll
        for (int k = 0; k < 8; k++) {
            int cg = wid * 2 + nt;
            uint2 v = __ldg(&g_F[5][0][(cg * 8 + k) * 32 + lane]);
            bh[nt][k][0] = v.x; bh[nt][k][1] = v.y;
            uint2 u = __ldg(&g_F[5][1][(cg * 8 + k) * 32 + lane]);
            bl[nt][k][0] = u.x; bl[nt][k][1] = u.y;
        }
    __syncthreads();

#pragma unroll
    for (int s = 0; s < 16; s++) {
        int item = tid + s * 256;
        int e = item >> 5, j = (item & 31) << 2;
        int r = row_s[e], c = col_s[e];
        float rd = rd_s[e];
        float4 a  = *(const float4*)&g_m1[r * HH + j];
        float4 b  = *(const float4*)&g_m2[c * HH + j];
        float4 w  = *(const float4*)&wd_s[j];
        float4 bb = *(const float4*)&b1_s[j];
        float v0 = fmaxf(a.x + b.x + rd * w.x + bb.x, 0.f);
        float v1 = fmaxf(a.y + b.y + rd * w.y + bb.y, 0.f);
        float v2 = fmaxf(a.z + b.z + rd * w.z + bb.z, 0.f);
        float v3 = fmaxf(a.w + b.w + rd * w.w + bb.w, 0.f);
        uint2 hv, lv;
        hilo4(v0, v1, v2, v3, hv, lv);
        int off = e * EK2_ASTRIDE + j * 2;
        *(uint2*)(A_hi + off) = hv;
        *(uint2*)(A_lo + off) = lv;
    }
    __syncthreads();

    {
        uint32_t hbase = smem_u32(A_hi);
        uint32_t lbase = smem_u32(A_lo);
        int aroff = (lane & 15) * EK2_ASTRIDE + ((lane >> 4) & 1) * 16;
#pragma unroll
        for (int m = 0; m < 8; m++) {
            float acc[2][4];
#pragma unroll
            for (int nt = 0; nt < 2; nt++)
#pragma unroll
                for (int q = 0; q < 4; q++) acc[nt][q] = 0.f;
#pragma unroll
            for (int k = 0; k < 8; k++) {
                uint32_t a = (m * 16) * EK2_ASTRIDE + k * 32 + aroff;
                uint32_t ah[4], al[4];
                ldmx4(ah, hbase + a);
                ldmx4(al, lbase + a);
#pragma unroll
                for (int nt = 0; nt < 2; nt++) {
                    mma_bf16(acc[nt], ah, bh[nt][k][0], bh[nt][k][1]);
                    mma_bf16(acc[nt], ah, bl[nt][k][0], bl[nt][k][1]);
                    mma_bf16(acc[nt], al, bh[nt][k][0], bh[nt][k][1]);
                }
            }
            int r0 = m * 16 + (lane >> 2);
            float p0 = 0.f, p1 = 0.f;
#pragma unroll
            for (int nt = 0; nt < 2; nt++) {
                int n = wid * 16 + nt * 8 + (lane & 3) * 2;
                p0 += fmaxf(acc[nt][0] + bc_s[n], 0.f) * cw2_s[n]
                    + fmaxf(acc[nt][1] + bc_s[n + 1], 0.f) * cw2_s[n + 1];
                p1 += fmaxf(acc[nt][2] + bc_s[n], 0.f) * cw2_s[n]
                    + fmaxf(acc[nt][3] + bc_s[n + 1], 0.f) * cw2_s[n + 1];
            }
            p0 += __shfl_xor_sync(0xffffffffu, p0, 1);
            p0 += __shfl_xor_sync(0xffffffffu, p0, 2);
            p1 += __shfl_xor_sync(0xffffffffu, p1, 1);
            p1 += __shfl_xor_sync(0xffffffffu, p1, 2);
            if ((lane & 3) == 0) {
                atomicAdd(&coordp[r0], p0);
                atomicAdd(&coordp[r0 + 8], p1);
            }
        }
    }
    __syncthreads();
    if (tid < 128) {
        float csum = coordp[tid] + cb2[0];
        red_add_v2(&g_scat[2 * row_s[tid]], p2a_s[tid] * csum, p2b_s[tid] * csum);
    }
}

__global__ void copy_x_kernel(const float* __restrict__ x, float* __restrict__ outx) {
    int i = blockIdx.x * blockDim.x + threadIdx.x;
    if (i < NN * 2) outx[i] = x[i];
}

// ---------------- launcher ---------------------------------------------------
extern "C" void kernel_launch(void* const* d_in, const int* in_sizes, int n_in,
                              void* d_out, int out_size) {
    const float* h0   = (const float*)d_in[0];
    const float* x    = (const float*)d_in[1];
    const int*   ei   = (const int*)d_in[2];
    const float* embW = (const float*)d_in[3];
    const float* embB = (const float*)d_in[4];
    const float* eW1  = (const float*)d_in[5];
    const float* eb1  = (const float*)d_in[6];
    const float* eW2  = (const float*)d_in[7];
    const float* eb2  = (const float*)d_in[8];
    const float* nW1  = (const float*)d_in[9];
    const float* nb1  = (const float*)d_in[10];
    const float* nW2  = (const float*)d_in[11];
    const float* nb2  = (const float*)d_in[12];
    const float* vW1  = (const float*)d_in[13];
    const float* vb1  = (const float*)d_in[14];
    const float* vW2  = (const float*)d_in[15];
    const float* vb2  = (const float*)d_in[16];
    const float* cW1  = (const float*)d_in[17];
    const float* cb1  = (const float*)d_in[18];
    const float* cW2  = (const float*)d_in[19];
    const float* cb2  = (const float*)d_in[20];

    float* out   = (float*)d_out;
    float* out_h = out;
    float* out_x = out + NN * HH;
    float* out_v = out + NN * HH + NN * 2;

    float *p_h, *p_macc;
    cudaGetSymbolAddress((void**)&p_h,    g_h);
    cudaGetSymbolAddress((void**)&p_macc, g_macc);

    cudaFuncSetAttribute(node_mma_m12, cudaFuncAttributeMaxDynamicSharedMemorySize, NM_SMEM);
    cudaFuncSetAttribute(node_mma_th, cudaFuncAttributeMaxDynamicSharedMemorySize, NM_SMEM);
    cudaFuncSetAttribute(node_mma_v, cudaFuncAttributeMaxDynamicSharedMemorySize, NM_SMEM);
    cudaFuncSetAttribute(edge2_kernel, cudaFuncAttributeMaxDynamicSharedMemorySize, EK2_SMEM);
    cudaFuncSetAttribute(prep_frag_kernel, cudaFuncAttributeMaxDynamicSharedMemorySize, 69632);

    const int GB = (NN + 127) / 128;

    // side streams + events, created fresh every call and destroyed before return
    cudaStream_t s1, s2;
    cudaStreamCreateWithFlags(&s1, cudaStreamNonBlocking);
    cudaStreamCreateWithFlags(&s2, cudaStreamNonBlocking);
    cudaEvent_t eFork, eSort, eFork2, eEdge, eEmb;
    cudaEventCreateWithFlags(&eFork,  cudaEventDisableTiming);
    cudaEventCreateWithFlags(&eSort,  cudaEventDisableTiming);
    cudaEventCreateWithFlags(&eFork2, cudaEventDisableTiming);
    cudaEventCreateWithFlags(&eEdge,  cudaEventDisableTiming);
    cudaEventCreateWithFlags(&eEmb,   cudaEventDisableTiming);

    cudaEventRecord(eFork, 0);

    // --- branch s1: sort pipeline ---
    cudaStreamWaitEvent(s1, eFork, 0);
    zero_cnt_scat_kernel<<<(NN * 2 + 255) / 256, 256, 0, s1>>>();
    count_kernel<<<(EE + 255) / 256, 256, 0, s1>>>(ei);
    scan1_kernel<<<SCAN_B, 256, 0, s1>>>();
    scan2_kernel<<<1, 256, 0, s1>>>();
    scan3_kernel<<<SCAN_B, 256, 0, s1>>>();
    scatter_kernel<<<(EE + 255) / 256, 256, 0, s1>>>(ei);
    cudaEventRecord(eSort, s1);

    // --- branch s2: copy x out + embed (input-only dependencies) ---
    cudaStreamWaitEvent(s2, eFork, 0);
    copy_x_kernel<<<(NN * 2 + 255) / 256, 256, 0, s2>>>(x, out_x);
    embed_kernel<<<NN / 2, 256, 0, s2>>>(h0, embW, embB);
    cudaEventRecord(eEmb, s2);

    // --- main: weight prep (transpose, then fragment tables) ---
    {
        dim3 g(128, 7);
        prep_all_kernel<<<g, 128>>>(eW1, nW1, nW2, vW1, eW2, cW1, eb2, cb1);
    }
    prep_frag_kernel<<<7, 256, 69632>>>();

    // ---- layer 0 ----
    cudaStreamWaitEvent(0, eEmb, 0);
    node_mma_m12<<<GB, 512, NM_SMEM>>>(p_h);
    cudaStreamWaitEvent(0, eSort, 0);
    macc_gather_kernel<<<(NN * 32 + 255) / 256, 256>>>(x, eW1, eb1);
    // th fused with m12 of layer 1 (phase C writes g_m1/g_m2 from h_new)
    node_mma_th<<<GB, 512, NM_SMEM>>>(p_h, p_macc, nb1, nb2, p_h, 1);

    // ---- layer 1 ----
    // m1/m2 ready now -> fork edge2 immediately, overlapping gather+th below
    cudaEventRecord(eFork2, 0);
    cudaStreamWaitEvent(s1, eFork2, 0);
    edge2_kernel<<<EE / 128, 256, EK2_SMEM, s1>>>(x, eW1, eb1, cW2, cb2);
    cudaEventRecord(eEdge, s1);
    macc_gather_kernel<<<(NN * 32 + 255) / 256, 256>>>(x, eW1, eb1);
    node_mma_th<<<GB, 512, NM_SMEM>>>(p_h, p_macc, nb1, nb2, out_h, 0);

    // join: v epilogue needs edge2's g_scat and th's out_h
    cudaStreamWaitEvent(0, eEdge, 0);
    node_mma_v<<<GB, 512, NM_SMEM>>>(out_h, vb1, vW2, vb2, out_v);

    // cleanup (allocation guard: return device memory to baseline)
    cudaEventDestroy(eFork);
    cudaEventDestroy(eSort);
    cudaEventDestroy(eFork2);
    cudaEventDestroy(eEdge);
    cudaEventDestroy(eEmb);
    cudaStreamDestroy(s1);
    cudaStreamDestroy(s2);
}